// round 9
// baseline (speedup 1.0000x reference)
#include <cuda_runtime.h>
#include <cuda_bf16.h>
#include <math.h>
#include <stdint.h>

#define DIM   1024
#define NUM_F 16
#define NB    4
#define SEQ   2048
#define MTOK  (NB * SEQ)   // 8192

// ======================= scratch (static device globals) ====================
__device__ __nv_bfloat16  g_ph[MTOK * SEQ];      // unnormalized exp(scores) hi
__device__ __nv_bfloat16  g_pl[MTOK * SEQ];      // lo
__device__ float          g_inv[MTOK];           // per-row 1/sum
__device__ __nv_bfloat16  g_xh[MTOK * DIM];
__device__ __nv_bfloat16  g_xl[MTOK * DIM];
__device__ __nv_bfloat16  g_wh[DIM * DIM];
__device__ __nv_bfloat16  g_wl[DIM * DIM];
__device__ __nv_bfloat16  g_vth[MTOK * DIM];     // v^T  [NB][DIM][SEQ] hi
__device__ __nv_bfloat16  g_vtl[MTOK * DIM];     // lo
__device__ float g_kanq[MTOK * NUM_F];
__device__ float g_kank[MTOK * NUM_F];
__device__ __nv_bfloat16 g_Ch[32 * DIM];         // folded C (rows 0-15 q, 16-31 k) hi
__device__ __nv_bfloat16 g_Cl[32 * DIM];         // lo
__device__ float g_cq[NUM_F];
__device__ float g_ck[NUM_F];
__device__ unsigned g_maxk_bits[NB];             // max |k|^2 per batch (fp32 bits)

// ======================= helpers ============================================
__device__ __forceinline__ uint32_t smem_u32(const void* p) {
    uint32_t a;
    asm("{ .reg .u64 t; cvta.to.shared.u64 t, %1; cvt.u32.u64 %0, t; }"
        : "=r"(a) : "l"(p));
    return a;
}
__device__ __forceinline__ void ldmx4(uint32_t* r, uint32_t addr) {
    asm volatile("ldmatrix.sync.aligned.m8n8.x4.shared.b16 {%0,%1,%2,%3}, [%4];"
        : "=r"(r[0]), "=r"(r[1]), "=r"(r[2]), "=r"(r[3]) : "r"(addr));
}
__device__ __forceinline__ void ldmx2(uint32_t* r, uint32_t addr) {
    asm volatile("ldmatrix.sync.aligned.m8n8.x2.shared.b16 {%0,%1}, [%2];"
        : "=r"(r[0]), "=r"(r[1]) : "r"(addr));
}
__device__ __forceinline__ void mma_bf16(float* c, const uint32_t* a, const uint32_t* b) {
    asm volatile("mma.sync.aligned.m16n8k16.row.col.f32.bf16.bf16.f32 "
        "{%0,%1,%2,%3}, {%4,%5,%6,%7}, {%8,%9}, {%0,%1,%2,%3};"
        : "+f"(c[0]), "+f"(c[1]), "+f"(c[2]), "+f"(c[3])
        : "r"(a[0]), "r"(a[1]), "r"(a[2]), "r"(a[3]), "r"(b[0]), "r"(b[1]));
}
__device__ __forceinline__ uint32_t pack2bf(float a, float b) {
    __nv_bfloat162 t = __floats2bfloat162_rn(a, b);
    return *(uint32_t*)&t;
}
// exp via FMA pipe (no MUFU): exp(x) = 2^(x*log2e), degree-6 poly on frac.
__device__ __forceinline__ float fexp(float x) {
    float t = fmaxf(x * 1.4426950408889634f, -120.f);
    float fl = floorf(t);
    float f = t - fl;
    float p = 1.5403530e-4f;
    p = fmaf(p, f, 1.3333558e-3f);
    p = fmaf(p, f, 9.6181291e-3f);
    p = fmaf(p, f, 5.5504109e-2f);
    p = fmaf(p, f, 2.4022651e-1f);
    p = fmaf(p, f, 6.9314718e-1f);
    p = fmaf(p, f, 1.0f);
    int i = (int)fl;
    return p * __int_as_float((uint32_t)(i + 127) << 23);
}

// ======================= K1: fold basis into Wq/Wk (bf16 split out) =========
__global__ void fold_kernel(const float* __restrict__ basis,
                            const float* __restrict__ Wq, const float* __restrict__ bq,
                            const float* __restrict__ Wk, const float* __restrict__ bk)
{
    if (blockIdx.x == 0 && blockIdx.y == 0 && threadIdx.x < NB)
        g_maxk_bits[threadIdx.x] = 0u;           // reset per call (deterministic)
    int d = blockIdx.x * blockDim.x + threadIdx.x;
    int f = blockIdx.y;
    const float* W  = (f < 16) ? Wq : Wk;
    const float* br = basis + (size_t)(f & 15) * DIM;
    float a = 0.f;
    for (int e = 0; e < DIM; e++)
        a = fmaf(br[e], W[(size_t)e * DIM + d], a);
    float h = __bfloat162float(__float2bfloat16(a));
    g_Ch[f * DIM + d] = __float2bfloat16(h);
    g_Cl[f * DIM + d] = __float2bfloat16(a - h);
    if (blockIdx.x == 0 && threadIdx.x == 0) {
        const float* bb = (f < 16) ? bq : bk;
        float s = 0.f;
        for (int e = 0; e < DIM; e++) s = fmaf(br[e], bb[e], s);
        if (f < 16) g_cq[f] = s; else g_ck[f - 16] = s;
    }
}

// ======================= split fp32 -> bf16 hi/lo ===========================
__global__ void split_kernel(const float* __restrict__ src,
                             __nv_bfloat16* __restrict__ hi,
                             __nv_bfloat16* __restrict__ lo)
{
    int i = blockIdx.x * blockDim.x + threadIdx.x;
    float4 v = ((const float4*)src)[i];
    float h0 = __bfloat162float(__float2bfloat16(v.x));
    float h1 = __bfloat162float(__float2bfloat16(v.y));
    float h2 = __bfloat162float(__float2bfloat16(v.z));
    float h3 = __bfloat162float(__float2bfloat16(v.w));
    ((uint2*)hi)[i] = make_uint2(pack2bf(h0, h1), pack2bf(h2, h3));
    ((uint2*)lo)[i] = make_uint2(pack2bf(v.x - h0, v.y - h1),
                                 pack2bf(v.z - h2, v.w - h3));
}

// ======================= K2: kan via mma.sync  [8192,32] = x @ Ccomb^T ======
// 64-row tiles (grid 128), 128 threads / 4 warps each 16x32.
#define KSTR 40
__global__ __launch_bounds__(128) void kan_mma_kernel()
{
    __shared__ __align__(16) __nv_bfloat16 sXh[64 * KSTR];
    __shared__ __align__(16) __nv_bfloat16 sXl[64 * KSTR];
    __shared__ __align__(16) __nv_bfloat16 sCh[32 * KSTR];
    __shared__ __align__(16) __nv_bfloat16 sCl[32 * KSTR];
    const int tid = threadIdx.x;
    const int lane = tid & 31, wid = tid >> 5;
    const int m0 = blockIdx.x * 64;

    const uint32_t uXh = smem_u32(sXh), uXl = smem_u32(sXl);
    const uint32_t uCh = smem_u32(sCh), uCl = smem_u32(sCl);

    const int xc0 = tid, xc1 = tid + 128;
    const int xr0 = xc0 >> 2, xk0 = (xc0 & 3) * 8;
    const int xr1 = xc1 >> 2, xk1 = (xc1 & 3) * 8;
    const uint32_t xs0 = (uint32_t)(xr0 * KSTR + xk0) * 2;
    const uint32_t xs1 = (uint32_t)(xr1 * KSTR + xk1) * 2;
    const int cr = tid >> 2, ck = (tid & 3) * 8;
    const uint32_t cs = (uint32_t)(cr * KSTR + ck) * 2;

    float acc[4][4];
#pragma unroll
    for (int ni = 0; ni < 4; ni++)
#pragma unroll
        for (int rr = 0; rr < 4; rr++) acc[ni][rr] = 0.f;

    const int arow = wid * 16 + (lane & 15);
    const int acol = (lane >> 4) * 8;
    const int brow = lane & 7;
    const int bcol = ((lane >> 3) & 1) * 8;

    for (int t = 0; t < DIM / 32; t++) {
        int k0 = t * 32;
        if (t > 0) __syncthreads();
        *(uint4*)((char*)sXh + xs0) = *(const uint4*)(g_xh + (size_t)(m0 + xr0) * DIM + k0 + xk0);
        *(uint4*)((char*)sXh + xs1) = *(const uint4*)(g_xh + (size_t)(m0 + xr1) * DIM + k0 + xk1);
        *(uint4*)((char*)sXl + xs0) = *(const uint4*)(g_xl + (size_t)(m0 + xr0) * DIM + k0 + xk0);
        *(uint4*)((char*)sXl + xs1) = *(const uint4*)(g_xl + (size_t)(m0 + xr1) * DIM + k0 + xk1);
        *(uint4*)((char*)sCh + cs)  = *(const uint4*)(g_Ch + (size_t)cr * DIM + k0 + ck);
        *(uint4*)((char*)sCl + cs)  = *(const uint4*)(g_Cl + (size_t)cr * DIM + k0 + ck);
        __syncthreads();
#pragma unroll
        for (int kk = 0; kk < 32; kk += 16) {
            uint32_t ah[4], al[4], bh[4][2], bl[4][2];
            uint32_t ad = (uint32_t)((arow * KSTR + kk + acol) * 2);
            ldmx4(ah, uXh + ad);
            ldmx4(al, uXl + ad);
#pragma unroll
            for (int ni = 0; ni < 4; ni++) {
                uint32_t bd = (uint32_t)(((brow + ni * 8) * KSTR + kk + bcol) * 2);
                ldmx2(bh[ni], uCh + bd);
                ldmx2(bl[ni], uCl + bd);
            }
#pragma unroll
            for (int ni = 0; ni < 4; ni++) {
                mma_bf16(acc[ni], ah, bh[ni]);
                mma_bf16(acc[ni], ah, bl[ni]);
                mma_bf16(acc[ni], al, bh[ni]);
            }
        }
    }

    int r0 = m0 + wid * 16 + (lane >> 2);
#pragma unroll
    for (int ni = 0; ni < 4; ni++) {
        int col = ni * 8 + (lane & 3) * 2;
#pragma unroll
        for (int cdx = 0; cdx < 2; cdx++) {
            int c = col + cdx;
            float bias = (c < 16) ? g_cq[c] : g_ck[c - 16];
            float* dst = (c < 16) ? g_kanq : g_kank;
            int f = c & 15;
            dst[(size_t)r0 * NUM_F + f]       = acc[ni][cdx]     + bias;
            dst[(size_t)(r0 + 8) * NUM_F + f] = acc[ni][cdx + 2] + bias;
        }
    }
}

// ======================= K2b: per-batch max |k|^2 ===========================
__global__ void knorm_kernel()
{
    int r = blockIdx.x * 256 + threadIdx.x;   // 0..8191
    const float4* kr = (const float4*)(g_kank + (size_t)r * NUM_F);
    float s = 0.f;
#pragma unroll
    for (int i = 0; i < 4; i++) {
        float4 v = kr[i];
        s += v.x * v.x + v.y * v.y + v.z * v.z + v.w * v.w;
    }
#pragma unroll
    for (int off = 16; off; off >>= 1)
        s = fmaxf(s, __shfl_xor_sync(0xffffffffu, s, off));
    if ((threadIdx.x & 31) == 0)
        atomicMax(&g_maxk_bits[r >> 11], __float_as_uint(s));
}

// ======================= K4: fused scores + softmax (single pass) ===========
// Deferred normalization: writes e = exp((s - |q|*maxK)/32) unnormalized as
// bf16 hi/lo, stores 1/sum per row; K5 epilogue multiplies by 1/sum.
#define ACH 256
__global__ __launch_bounds__(256) void attn_kernel()
{
    __shared__ __align__(16) float sK[ACH][20];
    const int tid = threadIdx.x;
    const int lane = tid & 31, wid = tid >> 5;
    const int blk = blockIdx.x;          // 128 blocks, 64 rows each
    const int b = blk >> 5;
    const int r0 = (blk & 31) * 64;
    const float maxk = sqrtf(__uint_as_float(g_maxk_bits[b]));
    const float inv32 = 1.0f / 32.0f;

    for (int p = 0; p < 2; p++) {
        const int rbase = r0 + wid * 8 + p * 4;
        float q[4][16], bound[4], sum[4];
#pragma unroll
        for (int i = 0; i < 4; i++) {
            const float* qr = g_kanq + (size_t)(b * SEQ + rbase + i) * NUM_F;
            float qs = 0.f;
#pragma unroll
            for (int f = 0; f < 16; f++) { q[i][f] = qr[f]; qs = fmaf(qr[f], qr[f], qs); }
            bound[i] = sqrtf(qs) * maxk;
            sum[i] = 0.f;
        }

        for (int c = 0; c < SEQ / ACH; c++) {
            __syncthreads();
#pragma unroll
            for (int u = 0; u < 4; u++) {
                int e4 = tid + u * 256;
                int kr = e4 >> 2, kf = (e4 & 3) * 4;
                *(float4*)&sK[kr][kf] =
                    *(const float4*)(g_kank + (size_t)(b * SEQ + c * ACH + kr) * NUM_F + kf);
            }
            __syncthreads();
#pragma unroll 2
            for (int kg = 0; kg < ACH / 32; kg++) {
                int jj = kg * 32 + lane;
                float k[16];
                *(float4*)&k[0]  = *(const float4*)&sK[jj][0];
                *(float4*)&k[4]  = *(const float4*)&sK[jj][4];
                *(float4*)&k[8]  = *(const float4*)&sK[jj][8];
                *(float4*)&k[12] = *(const float4*)&sK[jj][12];
                size_t jbase = (size_t)(b * SEQ) * SEQ + (size_t)c * ACH + jj;
#pragma unroll
                for (int i = 0; i < 4; i++) {
                    float s = 0.f;
#pragma unroll
                    for (int f = 0; f < 16; f++) s = fmaf(q[i][f], k[f], s);
                    float e = fexp((s - bound[i]) * inv32);
                    sum[i] += e;
                    float h = __bfloat162float(__float2bfloat16(e));
                    size_t idx = jbase + (size_t)(rbase + i) * SEQ;
                    g_ph[idx] = __float2bfloat16(h);
                    g_pl[idx] = __float2bfloat16(e - h);
                }
            }
        }
#pragma unroll
        for (int i = 0; i < 4; i++) {
#pragma unroll
            for (int off = 16; off; off >>= 1)
                sum[i] += __shfl_xor_sync(0xffffffffu, sum[i], off);
            if (lane == 0) g_inv[b * SEQ + rbase + i] = 1.0f / sum[i];
        }
        __syncthreads();
    }
}

// ======================= mma.sync GEMM: C = A @ B^T (bf16 split) ============
// Block 128x128, 8 warps each 64x32, BK=32, double-buffered LDG->reg->STS
// (R6 proven mainloop).
// TRANS=true : C -> transposed bf16 hi/lo into g_vth/g_vtl (+bias)
// TRANS=false: C -> fp32 row-major, scaled by g_inv[row] (softmax defer-norm)
#define MSTRIDE 40
#define TILE_B  (128 * MSTRIDE * 2)     // 10240 B
#define MM_SMEM (8 * TILE_B)            // 81920 B (also covers 128*132*4 epi)

template <bool TRANS>
__global__ __launch_bounds__(256, 1) void mma_gemm(
    const __nv_bfloat16* __restrict__ Ah_, const __nv_bfloat16* __restrict__ Al_,
    const __nv_bfloat16* __restrict__ Bh_, const __nv_bfloat16* __restrict__ Bl_,
    const float* __restrict__ bias, float* __restrict__ Cout,
    int Kdim, int Ndim, long sA, long sB, long sC)
{
    extern __shared__ char smem[];
    const uint32_t sb = smem_u32(smem);
    const int tid  = threadIdx.x;
    const int lane = tid & 31, wid = tid >> 5;
    const int warp_m = wid & 1, warp_n = wid >> 1;
    const int z  = blockIdx.z;
    const int m0 = blockIdx.y * 128, n0 = blockIdx.x * 128;

    const __nv_bfloat16* pAh = Ah_ + (size_t)z * sA;
    const __nv_bfloat16* pAl = Al_ + (size_t)z * sA;
    const __nv_bfloat16* pBh = Bh_ + (size_t)z * sB;
    const __nv_bfloat16* pBl = Bl_ + (size_t)z * sB;

    const int c1 = tid + 256;
    const int ar0 = tid >> 2, ak0 = (tid & 3) * 8;
    const int ar1 = c1 >> 2,  ak1 = (c1 & 3) * 8;
    const size_t gA0 = (size_t)(m0 + ar0) * Kdim + ak0;
    const size_t gA1 = (size_t)(m0 + ar1) * Kdim + ak1;
    const size_t gB0 = (size_t)(n0 + ar0) * Kdim + ak0;
    const size_t gB1 = (size_t)(n0 + ar1) * Kdim + ak1;
    const uint32_t s0 = (uint32_t)(ar0 * MSTRIDE + ak0) * 2;
    const uint32_t s1 = (uint32_t)(ar1 * MSTRIDE + ak1) * 2;

    float acc[4][4][4];
#pragma unroll
    for (int mi = 0; mi < 4; mi++)
#pragma unroll
        for (int ni = 0; ni < 4; ni++)
#pragma unroll
            for (int rr = 0; rr < 4; rr++) acc[mi][ni][rr] = 0.f;

    uint4 rg[8];
    const int T = Kdim >> 5;

#define LOADG(K0) do {                                                 \
        rg[0] = *(const uint4*)(pAh + gA0 + (K0));                     \
        rg[1] = *(const uint4*)(pAh + gA1 + (K0));                     \
        rg[2] = *(const uint4*)(pAl + gA0 + (K0));                     \
        rg[3] = *(const uint4*)(pAl + gA1 + (K0));                     \
        rg[4] = *(const uint4*)(pBh + gB0 + (K0));                     \
        rg[5] = *(const uint4*)(pBh + gB1 + (K0));                     \
        rg[6] = *(const uint4*)(pBl + gB0 + (K0));                     \
        rg[7] = *(const uint4*)(pBl + gB1 + (K0));                     \
    } while (0)

#define STORES(S) do {                                                 \
        char* base = smem + (S) * 4 * TILE_B;                          \
        *(uint4*)(base + s0)              = rg[0];                     \
        *(uint4*)(base + s1)              = rg[1];                     \
        *(uint4*)(base + TILE_B + s0)     = rg[2];                     \
        *(uint4*)(base + TILE_B + s1)     = rg[3];                     \
        *(uint4*)(base + 2 * TILE_B + s0) = rg[4];                     \
        *(uint4*)(base + 2 * TILE_B + s1) = rg[5];                     \
        *(uint4*)(base + 3 * TILE_B + s0) = rg[6];                     \
        *(uint4*)(base + 3 * TILE_B + s1) = rg[7];                     \
    } while (0)

    const int arow = warp_m * 64 + (lane & 15);
    const int acol = (lane >> 4) * 8;
    const int brow = warp_n * 32 + (lane & 7);
    const int bcol = ((lane >> 3) & 1) * 8;

    LOADG(0);
    STORES(0);
    __syncthreads();

    for (int t = 0; t < T; t++) {
        if (t + 1 < T) LOADG((t + 1) << 5);
        uint32_t base = sb + (uint32_t)(t & 1) * 4 * TILE_B;
#pragma unroll
        for (int kk = 0; kk < 32; kk += 16) {
            uint32_t ah[4][4], al[4][4], bh[4][2], bl[4][2];
#pragma unroll
            for (int mi = 0; mi < 4; mi++) {
                uint32_t ad = (uint32_t)(((arow + mi * 16) * MSTRIDE + kk + acol) * 2);
                ldmx4(ah[mi], base + ad);
                ldmx4(al[mi], base + TILE_B + ad);
            }
#pragma unroll
            for (int ni = 0; ni < 4; ni++) {
                uint32_t bd = (uint32_t)(((brow + ni * 8) * MSTRIDE + kk + bcol) * 2);
                ldmx2(bh[ni], base + 2 * TILE_B + bd);
                ldmx2(bl[ni], base + 3 * TILE_B + bd);
            }
#pragma unroll
            for (int mi = 0; mi < 4; mi++)
#pragma unroll
                for (int ni = 0; ni < 4; ni++) {
                    mma_bf16(acc[mi][ni], ah[mi], bh[ni]);
                    mma_bf16(acc[mi][ni], ah[mi], bl[ni]);
                    mma_bf16(acc[mi][ni], al[mi], bh[ni]);
                }
        }
        if (t + 1 < T) {
            STORES((t + 1) & 1);
            __syncthreads();
        }
    }
#undef LOADG
#undef STORES

    // ---------------- epilogue ----------------
    if (TRANS) {
        __syncthreads();
        float* st = (float*)smem;        // [128 n][132]
#pragma unroll
        for (int mi = 0; mi < 4; mi++) {
            int rowl = warp_m * 64 + mi * 16 + (lane >> 2);
#pragma unroll
            for (int ni = 0; ni < 4; ni++) {
                int coll = warp_n * 32 + ni * 8 + (lane & 3) * 2;
                float b0 = bias[n0 + coll], b1 = bias[n0 + coll + 1];
                st[coll * 132 + rowl]           = acc[mi][ni][0] + b0;
                st[(coll + 1) * 132 + rowl]     = acc[mi][ni][1] + b1;
                st[coll * 132 + rowl + 8]       = acc[mi][ni][2] + b0;
                st[(coll + 1) * 132 + rowl + 8] = acc[mi][ni][3] + b1;
            }
        }
        __syncthreads();
        int bz  = m0 >> 11;
        int m0s = m0 & (SEQ - 1);
        for (int w = tid; w < 128 * 64; w += 256) {
            int d = w >> 6, mp = w & 63;
            float v0 = st[d * 132 + mp * 2];
            float v1 = st[d * 132 + mp * 2 + 1];
            float h0 = __bfloat162float(__float2bfloat16(v0));
            float h1 = __bfloat162float(__float2bfloat16(v1));
            size_t idx = (((size_t)(bz * DIM + n0 + d) * SEQ + m0s) >> 1) + mp;
            ((uint32_t*)g_vth)[idx] = pack2bf(h0, h1);
            ((uint32_t*)g_vtl)[idx] = pack2bf(v0 - h0, v1 - h1);
        }
    } else {
        float* C = Cout + (size_t)z * sC;
#pragma unroll
        for (int mi = 0; mi < 4; mi++) {
            int rowl = warp_m * 64 + mi * 16 + (lane >> 2);
            float inv0 = g_inv[z * SEQ + m0 + rowl];
            float inv1 = g_inv[z * SEQ + m0 + rowl + 8];
#pragma unroll
            for (int ni = 0; ni < 4; ni++) {
                int col = n0 + warp_n * 32 + ni * 8 + (lane & 3) * 2;
                *(float2*)&C[(size_t)(m0 + rowl) * Ndim + col] =
                    make_float2(acc[mi][ni][0] * inv0, acc[mi][ni][1] * inv0);
                *(float2*)&C[(size_t)(m0 + rowl + 8) * Ndim + col] =
                    make_float2(acc[mi][ni][2] * inv1, acc[mi][ni][3] * inv1);
            }
        }
    }
}

// ======================= launch =============================================
extern "C" void kernel_launch(void* const* d_in, const int* in_sizes, int n_in,
                              void* d_out, int out_size)
{
    const float* x     = (const float*)d_in[0];
    const float* basis = (const float*)d_in[1];
    const float* Wq    = (const float*)d_in[2];
    const float* bq    = (const float*)d_in[3];
    const float* Wk    = (const float*)d_in[4];
    const float* bk    = (const float*)d_in[5];
    const float* Wv    = (const float*)d_in[6];
    const float* bv    = (const float*)d_in[7];
    float* out = (float*)d_out;

    __nv_bfloat16 *pxh, *pxl, *pwh, *pwl, *pph, *ppl, *pvth, *pvtl;
    cudaGetSymbolAddress((void**)&pxh, g_xh);
    cudaGetSymbolAddress((void**)&pxl, g_xl);
    cudaGetSymbolAddress((void**)&pwh, g_wh);
    cudaGetSymbolAddress((void**)&pwl, g_wl);
    cudaGetSymbolAddress((void**)&pph, g_ph);
    cudaGetSymbolAddress((void**)&ppl, g_pl);
    cudaGetSymbolAddress((void**)&pvth, g_vth);
    cudaGetSymbolAddress((void**)&pvtl, g_vtl);

    cudaFuncSetAttribute(mma_gemm<true>,  cudaFuncAttributeMaxDynamicSharedMemorySize, MM_SMEM);
    cudaFuncSetAttribute(mma_gemm<false>, cudaFuncAttributeMaxDynamicSharedMemorySize, MM_SMEM);

    // splits
    split_kernel<<<MTOK * DIM / 4 / 256, 256>>>(x, pxh, pxl);
    split_kernel<<<DIM * DIM / 4 / 256, 256>>>(Wv, pwh, pwl);

    // fold (bf16-split C + biases + maxk reset)
    fold_kernel<<<dim3(4, 32), 256>>>(basis, Wq, bq, Wk, bk);

    // kan via mma.sync (64-row tiles) + per-batch key-norm max
    kan_mma_kernel<<<MTOK / 64, 128>>>();
    knorm_kernel<<<MTOK / 256, 256>>>();

    // K3: v = x @ Wv^T + bv  -> vT (bf16 split)
    mma_gemm<true><<<dim3(DIM / 128, MTOK / 128, 1), 256, MM_SMEM>>>(
        pxh, pxl, pwh, pwl, bv, nullptr, DIM, DIM, 0L, 0L, 0L);

    // K4: fused scores + softmax (unnormalized exp + 1/sum)
    attn_kernel<<<MTOK / 64, 256>>>();

    // K5: out = (P~ @ v) * inv_sum
    mma_gemm<false><<<dim3(DIM / 128, SEQ / 128, NB), 256, MM_SMEM>>>(
        pph, ppl, pvth, pvtl, nullptr, out, SEQ, DIM,
        (long)SEQ * SEQ, (long)DIM * SEQ, (long)SEQ * DIM);
}

// round 10
// speedup vs baseline: 1.5012x; 1.5012x over previous
#include <cuda_runtime.h>
#include <cuda_bf16.h>
#include <math.h>
#include <stdint.h>

#define DIM   1024
#define NUM_F 16
#define NB    4
#define SEQ   2048
#define MTOK  (NB * SEQ)   // 8192

// ======================= scratch (static device globals) ====================
__device__ __nv_bfloat16  g_ph[MTOK * SEQ];      // unnormalized exp(scores) hi
__device__ __nv_bfloat16  g_pl[MTOK * SEQ];      // lo
__device__ float          g_inv[MTOK];           // per-row 1/sum
__device__ __nv_bfloat16  g_xh[MTOK * DIM];
__device__ __nv_bfloat16  g_xl[MTOK * DIM];
__device__ __nv_bfloat16  g_wh[DIM * DIM];
__device__ __nv_bfloat16  g_wl[DIM * DIM];
__device__ __nv_bfloat16  g_vth[MTOK * DIM];     // v^T  [NB][DIM][SEQ] hi
__device__ __nv_bfloat16  g_vtl[MTOK * DIM];     // lo
__device__ float g_kanq[MTOK * NUM_F];
__device__ float g_kank[MTOK * NUM_F];
__device__ __nv_bfloat16 g_Ch[32 * DIM];         // folded C (rows 0-15 q, 16-31 k) hi
__device__ __nv_bfloat16 g_Cl[32 * DIM];         // lo
__device__ float g_cq[NUM_F];
__device__ float g_ck[NUM_F];
__device__ unsigned g_maxk_bits[NB];             // max |k|^2 per batch (fp32 bits)

// ======================= helpers ============================================
__device__ __forceinline__ uint32_t smem_u32(const void* p) {
    uint32_t a;
    asm("{ .reg .u64 t; cvta.to.shared.u64 t, %1; cvt.u32.u64 %0, t; }"
        : "=r"(a) : "l"(p));
    return a;
}
__device__ __forceinline__ void ldmx4(uint32_t* r, uint32_t addr) {
    asm volatile("ldmatrix.sync.aligned.m8n8.x4.shared.b16 {%0,%1,%2,%3}, [%4];"
        : "=r"(r[0]), "=r"(r[1]), "=r"(r[2]), "=r"(r[3]) : "r"(addr));
}
__device__ __forceinline__ void ldmx2(uint32_t* r, uint32_t addr) {
    asm volatile("ldmatrix.sync.aligned.m8n8.x2.shared.b16 {%0,%1}, [%2];"
        : "=r"(r[0]), "=r"(r[1]) : "r"(addr));
}
__device__ __forceinline__ void mma_bf16(float* c, const uint32_t* a, const uint32_t* b) {
    asm volatile("mma.sync.aligned.m16n8k16.row.col.f32.bf16.bf16.f32 "
        "{%0,%1,%2,%3}, {%4,%5,%6,%7}, {%8,%9}, {%0,%1,%2,%3};"
        : "+f"(c[0]), "+f"(c[1]), "+f"(c[2]), "+f"(c[3])
        : "r"(a[0]), "r"(a[1]), "r"(a[2]), "r"(a[3]), "r"(b[0]), "r"(b[1]));
}
__device__ __forceinline__ uint32_t pack2bf(float a, float b) {
    __nv_bfloat162 t = __floats2bfloat162_rn(a, b);
    return *(uint32_t*)&t;
}
// exp via FMA pipe (no MUFU): exp(x) = 2^(x*log2e), degree-6 poly on frac.
__device__ __forceinline__ float fexp(float x) {
    float t = fmaxf(x * 1.4426950408889634f, -120.f);
    float fl = floorf(t);
    float f = t - fl;
    float p = 1.5403530e-4f;
    p = fmaf(p, f, 1.3333558e-3f);
    p = fmaf(p, f, 9.6181291e-3f);
    p = fmaf(p, f, 5.5504109e-2f);
    p = fmaf(p, f, 2.4022651e-1f);
    p = fmaf(p, f, 6.9314718e-1f);
    p = fmaf(p, f, 1.0f);
    int i = (int)fl;
    return p * __int_as_float((uint32_t)(i + 127) << 23);
}

// ======================= K1: fold basis into Wq/Wk (bf16 split out) =========
__global__ void fold_kernel(const float* __restrict__ basis,
                            const float* __restrict__ Wq, const float* __restrict__ bq,
                            const float* __restrict__ Wk, const float* __restrict__ bk)
{
    if (blockIdx.x == 0 && blockIdx.y == 0 && threadIdx.x < NB)
        g_maxk_bits[threadIdx.x] = 0u;           // reset per call (deterministic)
    int d = blockIdx.x * blockDim.x + threadIdx.x;
    int f = blockIdx.y;
    const float* W  = (f < 16) ? Wq : Wk;
    const float* br = basis + (size_t)(f & 15) * DIM;
    float a = 0.f;
    for (int e = 0; e < DIM; e++)
        a = fmaf(br[e], W[(size_t)e * DIM + d], a);
    float h = __bfloat162float(__float2bfloat16(a));
    g_Ch[f * DIM + d] = __float2bfloat16(h);
    g_Cl[f * DIM + d] = __float2bfloat16(a - h);
    if (blockIdx.x == 0 && threadIdx.x == 0) {
        const float* bb = (f < 16) ? bq : bk;
        float s = 0.f;
        for (int e = 0; e < DIM; e++) s = fmaf(br[e], bb[e], s);
        if (f < 16) g_cq[f] = s; else g_ck[f - 16] = s;
    }
}

// ======================= split fp32 -> bf16 hi/lo ===========================
__global__ void split_kernel(const float* __restrict__ src,
                             __nv_bfloat16* __restrict__ hi,
                             __nv_bfloat16* __restrict__ lo)
{
    int i = blockIdx.x * blockDim.x + threadIdx.x;
    float4 v = ((const float4*)src)[i];
    float h0 = __bfloat162float(__float2bfloat16(v.x));
    float h1 = __bfloat162float(__float2bfloat16(v.y));
    float h2 = __bfloat162float(__float2bfloat16(v.z));
    float h3 = __bfloat162float(__float2bfloat16(v.w));
    ((uint2*)hi)[i] = make_uint2(pack2bf(h0, h1), pack2bf(h2, h3));
    ((uint2*)lo)[i] = make_uint2(pack2bf(v.x - h0, v.y - h1),
                                 pack2bf(v.z - h2, v.w - h3));
}

// ======================= K2: kan via mma.sync  [8192,32] = x @ Ccomb^T ======
// 64-row tiles (grid 128), 128 threads / 4 warps each 16x32.
// Double-buffered: LDG of tile t+1 in registers while computing tile t.
#define KSTR 40
__global__ __launch_bounds__(128) void kan_mma_kernel()
{
    __shared__ __align__(16) __nv_bfloat16 sXh[2][64 * KSTR];
    __shared__ __align__(16) __nv_bfloat16 sXl[2][64 * KSTR];
    __shared__ __align__(16) __nv_bfloat16 sCh[2][32 * KSTR];
    __shared__ __align__(16) __nv_bfloat16 sCl[2][32 * KSTR];
    const int tid = threadIdx.x;
    const int lane = tid & 31, wid = tid >> 5;
    const int m0 = blockIdx.x * 64;

    const int xc1 = tid + 128;
    const int xr0 = tid >> 2, xk0 = (tid & 3) * 8;
    const int xr1 = xc1 >> 2, xk1 = (xc1 & 3) * 8;
    const uint32_t xs0 = (uint32_t)(xr0 * KSTR + xk0) * 2;
    const uint32_t xs1 = (uint32_t)(xr1 * KSTR + xk1) * 2;
    const int cr = tid >> 2, ck = (tid & 3) * 8;
    const uint32_t cs = (uint32_t)(cr * KSTR + ck) * 2;

    float acc[4][4];
#pragma unroll
    for (int ni = 0; ni < 4; ni++)
#pragma unroll
        for (int rr = 0; rr < 4; rr++) acc[ni][rr] = 0.f;

    const int arow = wid * 16 + (lane & 15);
    const int acol = (lane >> 4) * 8;
    const int brow = lane & 7;
    const int bcol = ((lane >> 3) & 1) * 8;

    uint4 r0v, r1v, r2v, r3v, r4v, r5v;
#define KLOAD(K0) do {                                                            \
        r0v = *(const uint4*)(g_xh + (size_t)(m0 + xr0) * DIM + (K0) + xk0);      \
        r1v = *(const uint4*)(g_xh + (size_t)(m0 + xr1) * DIM + (K0) + xk1);      \
        r2v = *(const uint4*)(g_xl + (size_t)(m0 + xr0) * DIM + (K0) + xk0);      \
        r3v = *(const uint4*)(g_xl + (size_t)(m0 + xr1) * DIM + (K0) + xk1);      \
        r4v = *(const uint4*)(g_Ch + (size_t)cr * DIM + (K0) + ck);               \
        r5v = *(const uint4*)(g_Cl + (size_t)cr * DIM + (K0) + ck);               \
    } while (0)
#define KSTORE(S) do {                                                            \
        *(uint4*)((char*)sXh[S] + xs0) = r0v;                                     \
        *(uint4*)((char*)sXh[S] + xs1) = r1v;                                     \
        *(uint4*)((char*)sXl[S] + xs0) = r2v;                                     \
        *(uint4*)((char*)sXl[S] + xs1) = r3v;                                     \
        *(uint4*)((char*)sCh[S] + cs)  = r4v;                                     \
        *(uint4*)((char*)sCl[S] + cs)  = r5v;                                     \
    } while (0)

    KLOAD(0);
    KSTORE(0);
    __syncthreads();

    const int T = DIM / 32;
    for (int t = 0; t < T; t++) {
        if (t + 1 < T) KLOAD((t + 1) * 32);
        const uint32_t uXh = smem_u32(sXh[t & 1]);
        const uint32_t uXl = smem_u32(sXl[t & 1]);
        const uint32_t uCh = smem_u32(sCh[t & 1]);
        const uint32_t uCl = smem_u32(sCl[t & 1]);
#pragma unroll
        for (int kk = 0; kk < 32; kk += 16) {
            uint32_t ah[4], al[4], bh[4][2], bl[4][2];
            uint32_t ad = (uint32_t)((arow * KSTR + kk + acol) * 2);
            ldmx4(ah, uXh + ad);
            ldmx4(al, uXl + ad);
#pragma unroll
            for (int ni = 0; ni < 4; ni++) {
                uint32_t bd = (uint32_t)(((brow + ni * 8) * KSTR + kk + bcol) * 2);
                ldmx2(bh[ni], uCh + bd);
                ldmx2(bl[ni], uCl + bd);
            }
#pragma unroll
            for (int ni = 0; ni < 4; ni++) {
                mma_bf16(acc[ni], ah, bh[ni]);
                mma_bf16(acc[ni], ah, bl[ni]);
                mma_bf16(acc[ni], al, bh[ni]);
            }
        }
        if (t + 1 < T) {
            __syncthreads();          // everyone done reading buf(t&1)? no — done reading via ldmatrix above
            KSTORE((t + 1) & 1);
            __syncthreads();
        }
    }
#undef KLOAD
#undef KSTORE

    int r0 = m0 + wid * 16 + (lane >> 2);
#pragma unroll
    for (int ni = 0; ni < 4; ni++) {
        int col = ni * 8 + (lane & 3) * 2;
#pragma unroll
        for (int cdx = 0; cdx < 2; cdx++) {
            int c = col + cdx;
            float bias = (c < 16) ? g_cq[c] : g_ck[c - 16];
            float* dst = (c < 16) ? g_kanq : g_kank;
            int f = c & 15;
            dst[(size_t)r0 * NUM_F + f]       = acc[ni][cdx]     + bias;
            dst[(size_t)(r0 + 8) * NUM_F + f] = acc[ni][cdx + 2] + bias;
        }
    }
}

// ======================= K2b: per-batch max |k|^2 ===========================
__global__ void knorm_kernel()
{
    int r = blockIdx.x * 256 + threadIdx.x;   // 0..8191
    const float4* kr = (const float4*)(g_kank + (size_t)r * NUM_F);
    float s = 0.f;
#pragma unroll
    for (int i = 0; i < 4; i++) {
        float4 v = kr[i];
        s += v.x * v.x + v.y * v.y + v.z * v.z + v.w * v.w;
    }
#pragma unroll
    for (int off = 16; off; off >>= 1)
        s = fmaxf(s, __shfl_xor_sync(0xffffffffu, s, off));
    if ((threadIdx.x & 31) == 0)
        atomicMax(&g_maxk_bits[r >> 11], __float_as_uint(s));
}

// ======================= K4: fused scores + softmax (single pass) ===========
#define ACH 256
__global__ __launch_bounds__(256) void attn_kernel()
{
    __shared__ __align__(16) float sK[ACH][20];
    const int tid = threadIdx.x;
    const int lane = tid & 31, wid = tid >> 5;
    const int blk = blockIdx.x;          // 128 blocks, 64 rows each
    const int b = blk >> 5;
    const int r0 = (blk & 31) * 64;
    const float maxk = sqrtf(__uint_as_float(g_maxk_bits[b]));
    const float inv32 = 1.0f / 32.0f;

    for (int p = 0; p < 2; p++) {
        const int rbase = r0 + wid * 8 + p * 4;
        float q[4][16], bound[4], sum[4];
#pragma unroll
        for (int i = 0; i < 4; i++) {
            const float* qr = g_kanq + (size_t)(b * SEQ + rbase + i) * NUM_F;
            float qs = 0.f;
#pragma unroll
            for (int f = 0; f < 16; f++) { q[i][f] = qr[f]; qs = fmaf(qr[f], qr[f], qs); }
            bound[i] = sqrtf(qs) * maxk;
            sum[i] = 0.f;
        }

        for (int c = 0; c < SEQ / ACH; c++) {
            __syncthreads();
#pragma unroll
            for (int u = 0; u < 4; u++) {
                int e4 = tid + u * 256;
                int kr = e4 >> 2, kf = (e4 & 3) * 4;
                *(float4*)&sK[kr][kf] =
                    *(const float4*)(g_kank + (size_t)(b * SEQ + c * ACH + kr) * NUM_F + kf);
            }
            __syncthreads();
#pragma unroll 2
            for (int kg = 0; kg < ACH / 32; kg++) {
                int jj = kg * 32 + lane;
                float k[16];
                *(float4*)&k[0]  = *(const float4*)&sK[jj][0];
                *(float4*)&k[4]  = *(const float4*)&sK[jj][4];
                *(float4*)&k[8]  = *(const float4*)&sK[jj][8];
                *(float4*)&k[12] = *(const float4*)&sK[jj][12];
                size_t jbase = (size_t)(b * SEQ) * SEQ + (size_t)c * ACH + jj;
#pragma unroll
                for (int i = 0; i < 4; i++) {
                    float s = 0.f;
#pragma unroll
                    for (int f = 0; f < 16; f++) s = fmaf(q[i][f], k[f], s);
                    float e = fexp((s - bound[i]) * inv32);
                    sum[i] += e;
                    float h = __bfloat162float(__float2bfloat16(e));
                    size_t idx = jbase + (size_t)(rbase + i) * SEQ;
                    g_ph[idx] = __float2bfloat16(h);
                    g_pl[idx] = __float2bfloat16(e - h);
                }
            }
        }
#pragma unroll
        for (int i = 0; i < 4; i++) {
#pragma unroll
            for (int off = 16; off; off >>= 1)
                sum[i] += __shfl_xor_sync(0xffffffffu, sum[i], off);
            if (lane == 0) g_inv[b * SEQ + rbase + i] = 1.0f / sum[i];
        }
        __syncthreads();
    }
}

// ======================= mma.sync GEMM: C = A @ B^T (bf16 split) ============
// Block 128x128, 8 warps each 64x32, BK=32, double-buffered LDG->reg->STS.
// TRANS=true : C -> transposed bf16 hi/lo into g_vth/g_vtl (+bias)
// TRANS=false: C -> fp32 row-major, scaled by g_inv[row] (softmax defer-norm)
#define MSTRIDE 40
#define TILE_B  (128 * MSTRIDE * 2)     // 10240 B
#define MM_SMEM (8 * TILE_B)            // 81920 B (also covers 128*132*4 epi)

template <bool TRANS>
__global__ __launch_bounds__(256, 1) void mma_gemm(
    const __nv_bfloat16* __restrict__ Ah_, const __nv_bfloat16* __restrict__ Al_,
    const __nv_bfloat16* __restrict__ Bh_, const __nv_bfloat16* __restrict__ Bl_,
    const float* __restrict__ bias, float* __restrict__ Cout,
    int Kdim, int Ndim, long sA, long sB, long sC)
{
    extern __shared__ char smem[];
    const uint32_t sb = smem_u32(smem);
    const int tid  = threadIdx.x;
    const int lane = tid & 31, wid = tid >> 5;
    const int warp_m = wid & 1, warp_n = wid >> 1;
    const int z  = blockIdx.z;
    const int m0 = blockIdx.y * 128, n0 = blockIdx.x * 128;

    const __nv_bfloat16* pAh = Ah_ + (size_t)z * sA;
    const __nv_bfloat16* pAl = Al_ + (size_t)z * sA;
    const __nv_bfloat16* pBh = Bh_ + (size_t)z * sB;
    const __nv_bfloat16* pBl = Bl_ + (size_t)z * sB;

    const int c1 = tid + 256;
    const int ar0 = tid >> 2, ak0 = (tid & 3) * 8;
    const int ar1 = c1 >> 2,  ak1 = (c1 & 3) * 8;
    const size_t gA0 = (size_t)(m0 + ar0) * Kdim + ak0;
    const size_t gA1 = (size_t)(m0 + ar1) * Kdim + ak1;
    const size_t gB0 = (size_t)(n0 + ar0) * Kdim + ak0;
    const size_t gB1 = (size_t)(n0 + ar1) * Kdim + ak1;
    const uint32_t s0 = (uint32_t)(ar0 * MSTRIDE + ak0) * 2;
    const uint32_t s1 = (uint32_t)(ar1 * MSTRIDE + ak1) * 2;

    float acc[4][4][4];
#pragma unroll
    for (int mi = 0; mi < 4; mi++)
#pragma unroll
        for (int ni = 0; ni < 4; ni++)
#pragma unroll
            for (int rr = 0; rr < 4; rr++) acc[mi][ni][rr] = 0.f;

    uint4 rg[8];
    const int T = Kdim >> 5;

#define LOADG(K0) do {                                                 \
        rg[0] = *(const uint4*)(pAh + gA0 + (K0));                     \
        rg[1] = *(const uint4*)(pAh + gA1 + (K0));                     \
        rg[2] = *(const uint4*)(pAl + gA0 + (K0));                     \
        rg[3] = *(const uint4*)(pAl + gA1 + (K0));                     \
        rg[4] = *(const uint4*)(pBh + gB0 + (K0));                     \
        rg[5] = *(const uint4*)(pBh + gB1 + (K0));                     \
        rg[6] = *(const uint4*)(pBl + gB0 + (K0));                     \
        rg[7] = *(const uint4*)(pBl + gB1 + (K0));                     \
    } while (0)

#define STORES(S) do {                                                 \
        char* base = smem + (S) * 4 * TILE_B;                          \
        *(uint4*)(base + s0)              = rg[0];                     \
        *(uint4*)(base + s1)              = rg[1];                     \
        *(uint4*)(base + TILE_B + s0)     = rg[2];                     \
        *(uint4*)(base + TILE_B + s1)     = rg[3];                     \
        *(uint4*)(base + 2 * TILE_B + s0) = rg[4];                     \
        *(uint4*)(base + 2 * TILE_B + s1) = rg[5];                     \
        *(uint4*)(base + 3 * TILE_B + s0) = rg[6];                     \
        *(uint4*)(base + 3 * TILE_B + s1) = rg[7];                     \
    } while (0)

    const int arow = warp_m * 64 + (lane & 15);
    const int acol = (lane >> 4) * 8;
    const int brow = warp_n * 32 + (lane & 7);
    const int bcol = ((lane >> 3) & 1) * 8;

    LOADG(0);
    STORES(0);
    __syncthreads();

    for (int t = 0; t < T; t++) {
        if (t + 1 < T) LOADG((t + 1) << 5);
        uint32_t base = sb + (uint32_t)(t & 1) * 4 * TILE_B;
#pragma unroll
        for (int kk = 0; kk < 32; kk += 16) {
            uint32_t ah[4][4], al[4][4], bh[4][2], bl[4][2];
#pragma unroll
            for (int mi = 0; mi < 4; mi++) {
                uint32_t ad = (uint32_t)(((arow + mi * 16) * MSTRIDE + kk + acol) * 2);
                ldmx4(ah[mi], base + ad);
                ldmx4(al[mi], base + TILE_B + ad);
            }
#pragma unroll
            for (int ni = 0; ni < 4; ni++) {
                uint32_t bd = (uint32_t)(((brow + ni * 8) * MSTRIDE + kk + bcol) * 2);
                ldmx2(bh[ni], base + 2 * TILE_B + bd);
                ldmx2(bl[ni], base + 3 * TILE_B + bd);
            }
#pragma unroll
            for (int mi = 0; mi < 4; mi++)
#pragma unroll
                for (int ni = 0; ni < 4; ni++) {
                    mma_bf16(acc[mi][ni], ah[mi], bh[ni]);
                    mma_bf16(acc[mi][ni], ah[mi], bl[ni]);
                    mma_bf16(acc[mi][ni], al[mi], bh[ni]);
                }
        }
        if (t + 1 < T) {
            STORES((t + 1) & 1);
            __syncthreads();
        }
    }
#undef LOADG
#undef STORES

    // ---------------- epilogue ----------------
    if (TRANS) {
        __syncthreads();
        float* st = (float*)smem;        // [128 n][132]
#pragma unroll
        for (int mi = 0; mi < 4; mi++) {
            int rowl = warp_m * 64 + mi * 16 + (lane >> 2);
#pragma unroll
            for (int ni = 0; ni < 4; ni++) {
                int coll = warp_n * 32 + ni * 8 + (lane & 3) * 2;
                float b0 = bias[n0 + coll], b1 = bias[n0 + coll + 1];
                st[coll * 132 + rowl]           = acc[mi][ni][0] + b0;
                st[(coll + 1) * 132 + rowl]     = acc[mi][ni][1] + b1;
                st[coll * 132 + rowl + 8]       = acc[mi][ni][2] + b0;
                st[(coll + 1) * 132 + rowl + 8] = acc[mi][ni][3] + b1;
            }
        }
        __syncthreads();
        int bz  = m0 >> 11;
        int m0s = m0 & (SEQ - 1);
        for (int w = tid; w < 128 * 64; w += 256) {
            int d = w >> 6, mp = w & 63;
            float v0 = st[d * 132 + mp * 2];
            float v1 = st[d * 132 + mp * 2 + 1];
            float h0 = __bfloat162float(__float2bfloat16(v0));
            float h1 = __bfloat162float(__float2bfloat16(v1));
            size_t idx = (((size_t)(bz * DIM + n0 + d) * SEQ + m0s) >> 1) + mp;
            ((uint32_t*)g_vth)[idx] = pack2bf(h0, h1);
            ((uint32_t*)g_vtl)[idx] = pack2bf(v0 - h0, v1 - h1);
        }
    } else {
        float* C = Cout + (size_t)z * sC;
#pragma unroll
        for (int mi = 0; mi < 4; mi++) {
            int rowl = warp_m * 64 + mi * 16 + (lane >> 2);
            float inv0 = g_inv[z * SEQ + m0 + rowl];
            float inv1 = g_inv[z * SEQ + m0 + rowl + 8];
#pragma unroll
            for (int ni = 0; ni < 4; ni++) {
                int col = n0 + warp_n * 32 + ni * 8 + (lane & 3) * 2;
                *(float2*)&C[(size_t)(m0 + rowl) * Ndim + col] =
                    make_float2(acc[mi][ni][0] * inv0, acc[mi][ni][1] * inv0);
                *(float2*)&C[(size_t)(m0 + rowl + 8) * Ndim + col] =
                    make_float2(acc[mi][ni][2] * inv1, acc[mi][ni][3] * inv1);
            }
        }
    }
}

// ======================= launch =============================================
extern "C" void kernel_launch(void* const* d_in, const int* in_sizes, int n_in,
                              void* d_out, int out_size)
{
    const float* x     = (const float*)d_in[0];
    const float* basis = (const float*)d_in[1];
    const float* Wq    = (const float*)d_in[2];
    const float* bq    = (const float*)d_in[3];
    const float* Wk    = (const float*)d_in[4];
    const float* bk    = (const float*)d_in[5];
    const float* Wv    = (const float*)d_in[6];
    const float* bv    = (const float*)d_in[7];
    float* out = (float*)d_out;

    __nv_bfloat16 *pxh, *pxl, *pwh, *pwl, *pph, *ppl, *pvth, *pvtl;
    cudaGetSymbolAddress((void**)&pxh, g_xh);
    cudaGetSymbolAddress((void**)&pxl, g_xl);
    cudaGetSymbolAddress((void**)&pwh, g_wh);
    cudaGetSymbolAddress((void**)&pwl, g_wl);
    cudaGetSymbolAddress((void**)&pph, g_ph);
    cudaGetSymbolAddress((void**)&ppl, g_pl);
    cudaGetSymbolAddress((void**)&pvth, g_vth);
    cudaGetSymbolAddress((void**)&pvtl, g_vtl);

    cudaFuncSetAttribute(mma_gemm<true>,  cudaFuncAttributeMaxDynamicSharedMemorySize, MM_SMEM);
    cudaFuncSetAttribute(mma_gemm<false>, cudaFuncAttributeMaxDynamicSharedMemorySize, MM_SMEM);

    // splits
    split_kernel<<<MTOK * DIM / 4 / 256, 256>>>(x, pxh, pxl);
    split_kernel<<<DIM * DIM / 4 / 256, 256>>>(Wv, pwh, pwl);

    // fold (bf16-split C + biases + maxk reset)
    fold_kernel<<<dim3(4, 32), 256>>>(basis, Wq, bq, Wk, bk);

    // kan via mma.sync (64-row tiles, double-buffered) + per-batch key max
    kan_mma_kernel<<<MTOK / 64, 128>>>();
    knorm_kernel<<<MTOK / 256, 256>>>();

    // K3: v = x @ Wv^T + bv  -> vT (bf16 split)
    mma_gemm<true><<<dim3(DIM / 128, MTOK / 128, 1), 256, MM_SMEM>>>(
        pxh, pxl, pwh, pwl, bv, nullptr, DIM, DIM, 0L, 0L, 0L);

    // K4: fused scores + softmax (unnormalized exp + 1/sum)
    attn_kernel<<<MTOK / 64, 256>>>();

    // K5: out = (P~ @ v) * inv_sum
    mma_gemm<false><<<dim3(DIM / 128, SEQ / 128, NB), 256, MM_SMEM>>>(
        pph, ppl, pvth, pvtl, nullptr, out, SEQ, DIM,
        (long)SEQ * SEQ, (long)DIM * SEQ, (long)SEQ * DIM);
}

// round 11
// speedup vs baseline: 1.5891x; 1.0586x over previous
#include <cuda_runtime.h>
#include <cuda_bf16.h>
#include <cuda_fp16.h>
#include <math.h>
#include <stdint.h>

#define DIM   1024
#define NUM_F 16
#define NB    4
#define SEQ   2048
#define MTOK  (NB * SEQ)   // 8192

// ======================= scratch (static device globals) ====================
__device__ __half         g_ph[MTOK * SEQ];      // unnormalized exp(scores), fp16
__device__ float          g_inv[MTOK];           // per-row 1/sum
__device__ __nv_bfloat16  g_xh[MTOK * DIM];
__device__ __nv_bfloat16  g_xl[MTOK * DIM];
__device__ __nv_bfloat16  g_wh[DIM * DIM];
__device__ __nv_bfloat16  g_wl[DIM * DIM];
__device__ __half         g_vth[MTOK * DIM];     // v^T [NB][DIM][SEQ] fp16 hi
__device__ __half         g_vtl[MTOK * DIM];     // fp16 lo
__device__ float g_kanq[MTOK * NUM_F];
__device__ float g_kank[MTOK * NUM_F];
__device__ __nv_bfloat16 g_Ch[32 * DIM];         // folded C (rows 0-15 q, 16-31 k) hi
__device__ __nv_bfloat16 g_Cl[32 * DIM];         // lo
__device__ float g_cq[NUM_F];
__device__ float g_ck[NUM_F];
__device__ unsigned g_maxk_bits[NB];             // max |k|^2 per batch (fp32 bits)

// ======================= helpers ============================================
__device__ __forceinline__ uint32_t smem_u32(const void* p) {
    uint32_t a;
    asm("{ .reg .u64 t; cvta.to.shared.u64 t, %1; cvt.u32.u64 %0, t; }"
        : "=r"(a) : "l"(p));
    return a;
}
__device__ __forceinline__ void ldmx4(uint32_t* r, uint32_t addr) {
    asm volatile("ldmatrix.sync.aligned.m8n8.x4.shared.b16 {%0,%1,%2,%3}, [%4];"
        : "=r"(r[0]), "=r"(r[1]), "=r"(r[2]), "=r"(r[3]) : "r"(addr));
}
__device__ __forceinline__ void ldmx2(uint32_t* r, uint32_t addr) {
    asm volatile("ldmatrix.sync.aligned.m8n8.x2.shared.b16 {%0,%1}, [%2];"
        : "=r"(r[0]), "=r"(r[1]) : "r"(addr));
}
__device__ __forceinline__ void mma_bf16(float* c, const uint32_t* a, const uint32_t* b) {
    asm volatile("mma.sync.aligned.m16n8k16.row.col.f32.bf16.bf16.f32 "
        "{%0,%1,%2,%3}, {%4,%5,%6,%7}, {%8,%9}, {%0,%1,%2,%3};"
        : "+f"(c[0]), "+f"(c[1]), "+f"(c[2]), "+f"(c[3])
        : "r"(a[0]), "r"(a[1]), "r"(a[2]), "r"(a[3]), "r"(b[0]), "r"(b[1]));
}
__device__ __forceinline__ void mma_f16(float* c, const uint32_t* a, const uint32_t* b) {
    asm volatile("mma.sync.aligned.m16n8k16.row.col.f32.f16.f16.f32 "
        "{%0,%1,%2,%3}, {%4,%5,%6,%7}, {%8,%9}, {%0,%1,%2,%3};"
        : "+f"(c[0]), "+f"(c[1]), "+f"(c[2]), "+f"(c[3])
        : "r"(a[0]), "r"(a[1]), "r"(a[2]), "r"(a[3]), "r"(b[0]), "r"(b[1]));
}
__device__ __forceinline__ uint32_t pack2bf(float a, float b) {
    __nv_bfloat162 t = __floats2bfloat162_rn(a, b);
    return *(uint32_t*)&t;
}
__device__ __forceinline__ uint32_t pack2hf(float a, float b) {
    __half2 t = __floats2half2_rn(a, b);
    return *(uint32_t*)&t;
}
// exp via FMA pipe (no MUFU): exp(x) = 2^(x*log2e), degree-6 poly on frac.
__device__ __forceinline__ float fexp(float x) {
    float t = fmaxf(x * 1.4426950408889634f, -120.f);
    float fl = floorf(t);
    float f = t - fl;
    float p = 1.5403530e-4f;
    p = fmaf(p, f, 1.3333558e-3f);
    p = fmaf(p, f, 9.6181291e-3f);
    p = fmaf(p, f, 5.5504109e-2f);
    p = fmaf(p, f, 2.4022651e-1f);
    p = fmaf(p, f, 6.9314718e-1f);
    p = fmaf(p, f, 1.0f);
    int i = (int)fl;
    return p * __int_as_float((uint32_t)(i + 127) << 23);
}

// ======================= K1: fold basis into Wq/Wk (bf16 split out) =========
__global__ void fold_kernel(const float* __restrict__ basis,
                            const float* __restrict__ Wq, const float* __restrict__ bq,
                            const float* __restrict__ Wk, const float* __restrict__ bk)
{
    if (blockIdx.x == 0 && blockIdx.y == 0 && threadIdx.x < NB)
        g_maxk_bits[threadIdx.x] = 0u;           // reset per call (deterministic)
    int d = blockIdx.x * blockDim.x + threadIdx.x;
    int f = blockIdx.y;
    const float* W  = (f < 16) ? Wq : Wk;
    const float* br = basis + (size_t)(f & 15) * DIM;
    float a = 0.f;
    for (int e = 0; e < DIM; e++)
        a = fmaf(br[e], W[(size_t)e * DIM + d], a);
    float h = __bfloat162float(__float2bfloat16(a));
    g_Ch[f * DIM + d] = __float2bfloat16(h);
    g_Cl[f * DIM + d] = __float2bfloat16(a - h);
    if (blockIdx.x == 0 && threadIdx.x == 0) {
        const float* bb = (f < 16) ? bq : bk;
        float s = 0.f;
        for (int e = 0; e < DIM; e++) s = fmaf(br[e], bb[e], s);
        if (f < 16) g_cq[f] = s; else g_ck[f - 16] = s;
    }
}

// ======================= split fp32 -> bf16 hi/lo ===========================
__global__ void split_kernel(const float* __restrict__ src,
                             __nv_bfloat16* __restrict__ hi,
                             __nv_bfloat16* __restrict__ lo)
{
    int i = blockIdx.x * blockDim.x + threadIdx.x;
    float4 v = ((const float4*)src)[i];
    float h0 = __bfloat162float(__float2bfloat16(v.x));
    float h1 = __bfloat162float(__float2bfloat16(v.y));
    float h2 = __bfloat162float(__float2bfloat16(v.z));
    float h3 = __bfloat162float(__float2bfloat16(v.w));
    ((uint2*)hi)[i] = make_uint2(pack2bf(h0, h1), pack2bf(h2, h3));
    ((uint2*)lo)[i] = make_uint2(pack2bf(v.x - h0, v.y - h1),
                                 pack2bf(v.z - h2, v.w - h3));
}

// ======================= K2: kan via mma.sync  [8192,32] = x @ Ccomb^T ======
#define KSTR 40
__global__ __launch_bounds__(128) void kan_mma_kernel()
{
    __shared__ __align__(16) __nv_bfloat16 sXh[2][64 * KSTR];
    __shared__ __align__(16) __nv_bfloat16 sXl[2][64 * KSTR];
    __shared__ __align__(16) __nv_bfloat16 sCh[2][32 * KSTR];
    __shared__ __align__(16) __nv_bfloat16 sCl[2][32 * KSTR];
    const int tid = threadIdx.x;
    const int lane = tid & 31, wid = tid >> 5;
    const int m0 = blockIdx.x * 64;

    const int xc1 = tid + 128;
    const int xr0 = tid >> 2, xk0 = (tid & 3) * 8;
    const int xr1 = xc1 >> 2, xk1 = (xc1 & 3) * 8;
    const uint32_t xs0 = (uint32_t)(xr0 * KSTR + xk0) * 2;
    const uint32_t xs1 = (uint32_t)(xr1 * KSTR + xk1) * 2;
    const int cr = tid >> 2, ck = (tid & 3) * 8;
    const uint32_t cs = (uint32_t)(cr * KSTR + ck) * 2;

    float acc[4][4];
#pragma unroll
    for (int ni = 0; ni < 4; ni++)
#pragma unroll
        for (int rr = 0; rr < 4; rr++) acc[ni][rr] = 0.f;

    const int arow = wid * 16 + (lane & 15);
    const int acol = (lane >> 4) * 8;
    const int brow = lane & 7;
    const int bcol = ((lane >> 3) & 1) * 8;

    uint4 r0v, r1v, r2v, r3v, r4v, r5v;
#define KLOAD(K0) do {                                                            \
        r0v = *(const uint4*)(g_xh + (size_t)(m0 + xr0) * DIM + (K0) + xk0);      \
        r1v = *(const uint4*)(g_xh + (size_t)(m0 + xr1) * DIM + (K0) + xk1);      \
        r2v = *(const uint4*)(g_xl + (size_t)(m0 + xr0) * DIM + (K0) + xk0);      \
        r3v = *(const uint4*)(g_xl + (size_t)(m0 + xr1) * DIM + (K0) + xk1);      \
        r4v = *(const uint4*)(g_Ch + (size_t)cr * DIM + (K0) + ck);               \
        r5v = *(const uint4*)(g_Cl + (size_t)cr * DIM + (K0) + ck);               \
    } while (0)
#define KSTORE(S) do {                                                            \
        *(uint4*)((char*)sXh[S] + xs0) = r0v;                                     \
        *(uint4*)((char*)sXh[S] + xs1) = r1v;                                     \
        *(uint4*)((char*)sXl[S] + xs0) = r2v;                                     \
        *(uint4*)((char*)sXl[S] + xs1) = r3v;                                     \
        *(uint4*)((char*)sCh[S] + cs)  = r4v;                                     \
        *(uint4*)((char*)sCl[S] + cs)  = r5v;                                     \
    } while (0)

    KLOAD(0);
    KSTORE(0);
    __syncthreads();

    const int T = DIM / 32;
    for (int t = 0; t < T; t++) {
        if (t + 1 < T) KLOAD((t + 1) * 32);
        const uint32_t uXh = smem_u32(sXh[t & 1]);
        const uint32_t uXl = smem_u32(sXl[t & 1]);
        const uint32_t uCh = smem_u32(sCh[t & 1]);
        const uint32_t uCl = smem_u32(sCl[t & 1]);
#pragma unroll
        for (int kk = 0; kk < 32; kk += 16) {
            uint32_t ah[4], al[4], bh[4][2], bl[4][2];
            uint32_t ad = (uint32_t)((arow * KSTR + kk + acol) * 2);
            ldmx4(ah, uXh + ad);
            ldmx4(al, uXl + ad);
#pragma unroll
            for (int ni = 0; ni < 4; ni++) {
                uint32_t bd = (uint32_t)(((brow + ni * 8) * KSTR + kk + bcol) * 2);
                ldmx2(bh[ni], uCh + bd);
                ldmx2(bl[ni], uCl + bd);
            }
#pragma unroll
            for (int ni = 0; ni < 4; ni++) {
                mma_bf16(acc[ni], ah, bh[ni]);
                mma_bf16(acc[ni], ah, bl[ni]);
                mma_bf16(acc[ni], al, bh[ni]);
            }
        }
        if (t + 1 < T) {
            __syncthreads();
            KSTORE((t + 1) & 1);
            __syncthreads();
        }
    }
#undef KLOAD
#undef KSTORE

    int r0 = m0 + wid * 16 + (lane >> 2);
#pragma unroll
    for (int ni = 0; ni < 4; ni++) {
        int col = ni * 8 + (lane & 3) * 2;
#pragma unroll
        for (int cdx = 0; cdx < 2; cdx++) {
            int c = col + cdx;
            float bias = (c < 16) ? g_cq[c] : g_ck[c - 16];
            float* dst = (c < 16) ? g_kanq : g_kank;
            int f = c & 15;
            dst[(size_t)r0 * NUM_F + f]       = acc[ni][cdx]     + bias;
            dst[(size_t)(r0 + 8) * NUM_F + f] = acc[ni][cdx + 2] + bias;
        }
    }
}

// ======================= K2b: per-batch max |k|^2 ===========================
__global__ void knorm_kernel()
{
    int r = blockIdx.x * 256 + threadIdx.x;   // 0..8191
    const float4* kr = (const float4*)(g_kank + (size_t)r * NUM_F);
    float s = 0.f;
#pragma unroll
    for (int i = 0; i < 4; i++) {
        float4 v = kr[i];
        s += v.x * v.x + v.y * v.y + v.z * v.z + v.w * v.w;
    }
#pragma unroll
    for (int off = 16; off; off >>= 1)
        s = fmaxf(s, __shfl_xor_sync(0xffffffffu, s, off));
    if ((threadIdx.x & 31) == 0)
        atomicMax(&g_maxk_bits[r >> 11], __float_as_uint(s));
}

// ======================= K4: fused scores + softmax (single pass) ===========
// Writes e = exp((s - |q|*maxK)/32) unnormalized as fp16; 1/sum per row.
#define ACH 256
__global__ __launch_bounds__(256) void attn_kernel()
{
    __shared__ __align__(16) float sK[ACH][20];
    const int tid = threadIdx.x;
    const int lane = tid & 31, wid = tid >> 5;
    const int blk = blockIdx.x;          // 128 blocks, 64 rows each
    const int b = blk >> 5;
    const int r0 = (blk & 31) * 64;
    const float maxk = sqrtf(__uint_as_float(g_maxk_bits[b]));
    const float inv32 = 1.0f / 32.0f;

    for (int p = 0; p < 2; p++) {
        const int rbase = r0 + wid * 8 + p * 4;
        float q[4][16], bound[4], sum[4];
#pragma unroll
        for (int i = 0; i < 4; i++) {
            const float* qr = g_kanq + (size_t)(b * SEQ + rbase + i) * NUM_F;
            float qs = 0.f;
#pragma unroll
            for (int f = 0; f < 16; f++) { q[i][f] = qr[f]; qs = fmaf(qr[f], qr[f], qs); }
            bound[i] = sqrtf(qs) * maxk;
            sum[i] = 0.f;
        }

        for (int c = 0; c < SEQ / ACH; c++) {
            __syncthreads();
#pragma unroll
            for (int u = 0; u < 4; u++) {
                int e4 = tid + u * 256;
                int kr = e4 >> 2, kf = (e4 & 3) * 4;
                *(float4*)&sK[kr][kf] =
                    *(const float4*)(g_kank + (size_t)(b * SEQ + c * ACH + kr) * NUM_F + kf);
            }
            __syncthreads();
#pragma unroll 2
            for (int kg = 0; kg < ACH / 32; kg++) {
                int jj = kg * 32 + lane;
                float k[16];
                *(float4*)&k[0]  = *(const float4*)&sK[jj][0];
                *(float4*)&k[4]  = *(const float4*)&sK[jj][4];
                *(float4*)&k[8]  = *(const float4*)&sK[jj][8];
                *(float4*)&k[12] = *(const float4*)&sK[jj][12];
                size_t jbase = (size_t)(b * SEQ) * SEQ + (size_t)c * ACH + jj;
#pragma unroll
                for (int i = 0; i < 4; i++) {
                    float s = 0.f;
#pragma unroll
                    for (int f = 0; f < 16; f++) s = fmaf(q[i][f], k[f], s);
                    float e = fexp((s - bound[i]) * inv32);
                    sum[i] += e;
                    g_ph[jbase + (size_t)(rbase + i) * SEQ] = __float2half(e);
                }
            }
        }
#pragma unroll
        for (int i = 0; i < 4; i++) {
#pragma unroll
            for (int off = 16; off; off >>= 1)
                sum[i] += __shfl_xor_sync(0xffffffffu, sum[i], off);
            if (lane == 0) g_inv[b * SEQ + rbase + i] = 1.0f / sum[i];
        }
        __syncthreads();
    }
}

// ======================= K3: v = x @ Wv^T + bv (bf16 3-product) =============
// Block 128x128, 8 warps each 64x32, BK=32, double-buffered LDG->reg->STS.
// Epilogue: transpose, write vT as fp16 hi/lo into g_vth/g_vtl.
#define MSTRIDE 40
#define TILE_B  (128 * MSTRIDE * 2)     // 10240 B
#define MM_SMEM (8 * TILE_B)            // 81920 B (also covers 128*132*4 epi)

__global__ __launch_bounds__(256, 1) void mma_gemm_xw(const float* __restrict__ bias)
{
    extern __shared__ char smem[];
    const uint32_t sb = smem_u32(smem);
    const int tid  = threadIdx.x;
    const int lane = tid & 31, wid = tid >> 5;
    const int warp_m = wid & 1, warp_n = wid >> 1;
    const int m0 = blockIdx.y * 128, n0 = blockIdx.x * 128;

    const __nv_bfloat16* pAh = g_xh;
    const __nv_bfloat16* pAl = g_xl;
    const __nv_bfloat16* pBh = g_wh;
    const __nv_bfloat16* pBl = g_wl;

    const int c1 = tid + 256;
    const int ar0 = tid >> 2, ak0 = (tid & 3) * 8;
    const int ar1 = c1 >> 2,  ak1 = (c1 & 3) * 8;
    const size_t gA0 = (size_t)(m0 + ar0) * DIM + ak0;
    const size_t gA1 = (size_t)(m0 + ar1) * DIM + ak1;
    const size_t gB0 = (size_t)(n0 + ar0) * DIM + ak0;
    const size_t gB1 = (size_t)(n0 + ar1) * DIM + ak1;
    const uint32_t s0 = (uint32_t)(ar0 * MSTRIDE + ak0) * 2;
    const uint32_t s1 = (uint32_t)(ar1 * MSTRIDE + ak1) * 2;

    float acc[4][4][4];
#pragma unroll
    for (int mi = 0; mi < 4; mi++)
#pragma unroll
        for (int ni = 0; ni < 4; ni++)
#pragma unroll
            for (int rr = 0; rr < 4; rr++) acc[mi][ni][rr] = 0.f;

    uint4 rg[8];
    const int T = DIM >> 5;

#define LOADG(K0) do {                                                 \
        rg[0] = *(const uint4*)(pAh + gA0 + (K0));                     \
        rg[1] = *(const uint4*)(pAh + gA1 + (K0));                     \
        rg[2] = *(const uint4*)(pAl + gA0 + (K0));                     \
        rg[3] = *(const uint4*)(pAl + gA1 + (K0));                     \
        rg[4] = *(const uint4*)(pBh + gB0 + (K0));                     \
        rg[5] = *(const uint4*)(pBh + gB1 + (K0));                     \
        rg[6] = *(const uint4*)(pBl + gB0 + (K0));                     \
        rg[7] = *(const uint4*)(pBl + gB1 + (K0));                     \
    } while (0)

#define STORES(S) do {                                                 \
        char* base = smem + (S) * 4 * TILE_B;                          \
        *(uint4*)(base + s0)              = rg[0];                     \
        *(uint4*)(base + s1)              = rg[1];                     \
        *(uint4*)(base + TILE_B + s0)     = rg[2];                     \
        *(uint4*)(base + TILE_B + s1)     = rg[3];                     \
        *(uint4*)(base + 2 * TILE_B + s0) = rg[4];                     \
        *(uint4*)(base + 2 * TILE_B + s1) = rg[5];                     \
        *(uint4*)(base + 3 * TILE_B + s0) = rg[6];                     \
        *(uint4*)(base + 3 * TILE_B + s1) = rg[7];                     \
    } while (0)

    const int arow = warp_m * 64 + (lane & 15);
    const int acol = (lane >> 4) * 8;
    const int brow = warp_n * 32 + (lane & 7);
    const int bcol = ((lane >> 3) & 1) * 8;

    LOADG(0);
    STORES(0);
    __syncthreads();

    for (int t = 0; t < T; t++) {
        if (t + 1 < T) LOADG((t + 1) << 5);
        uint32_t base = sb + (uint32_t)(t & 1) * 4 * TILE_B;
#pragma unroll
        for (int kk = 0; kk < 32; kk += 16) {
            uint32_t ah[4][4], al[4][4], bh[4][2], bl[4][2];
#pragma unroll
            for (int mi = 0; mi < 4; mi++) {
                uint32_t ad = (uint32_t)(((arow + mi * 16) * MSTRIDE + kk + acol) * 2);
                ldmx4(ah[mi], base + ad);
                ldmx4(al[mi], base + TILE_B + ad);
            }
#pragma unroll
            for (int ni = 0; ni < 4; ni++) {
                uint32_t bd = (uint32_t)(((brow + ni * 8) * MSTRIDE + kk + bcol) * 2);
                ldmx2(bh[ni], base + 2 * TILE_B + bd);
                ldmx2(bl[ni], base + 3 * TILE_B + bd);
            }
#pragma unroll
            for (int mi = 0; mi < 4; mi++)
#pragma unroll
                for (int ni = 0; ni < 4; ni++) {
                    mma_bf16(acc[mi][ni], ah[mi], bh[ni]);
                    mma_bf16(acc[mi][ni], ah[mi], bl[ni]);
                    mma_bf16(acc[mi][ni], al[mi], bh[ni]);
                }
        }
        if (t + 1 < T) {
            STORES((t + 1) & 1);
            __syncthreads();
        }
    }
#undef LOADG
#undef STORES

    // epilogue: transpose in smem, write fp16 hi/lo vT
    __syncthreads();
    float* st = (float*)smem;        // [128 n][132]
#pragma unroll
    for (int mi = 0; mi < 4; mi++) {
        int rowl = warp_m * 64 + mi * 16 + (lane >> 2);
#pragma unroll
        for (int ni = 0; ni < 4; ni++) {
            int coll = warp_n * 32 + ni * 8 + (lane & 3) * 2;
            float b0 = bias[n0 + coll], b1 = bias[n0 + coll + 1];
            st[coll * 132 + rowl]           = acc[mi][ni][0] + b0;
            st[(coll + 1) * 132 + rowl]     = acc[mi][ni][1] + b1;
            st[coll * 132 + rowl + 8]       = acc[mi][ni][2] + b0;
            st[(coll + 1) * 132 + rowl + 8] = acc[mi][ni][3] + b1;
        }
    }
    __syncthreads();
    int bz  = m0 >> 11;
    int m0s = m0 & (SEQ - 1);
    for (int w = tid; w < 128 * 64; w += 256) {
        int d = w >> 6, mp = w & 63;
        float v0 = st[d * 132 + mp * 2];
        float v1 = st[d * 132 + mp * 2 + 1];
        float h0 = __half2float(__float2half(v0));
        float h1 = __half2float(__float2half(v1));
        size_t idx = (((size_t)(bz * DIM + n0 + d) * SEQ + m0s) >> 1) + mp;
        ((uint32_t*)g_vth)[idx] = pack2hf(v0, v1);
        ((uint32_t*)g_vtl)[idx] = pack2hf(v0 - h0, v1 - h1);
    }
}

// ======================= K5: out = (P @ v) * inv  (fp16, 2-product) =========
// A = P fp16 [SEQ,SEQ] K-major, B = vT fp16 hi/lo [DIM,SEQ]. 3 tiles/stage.
#define PV_SMEM (6 * TILE_B)            // 61440 B

__global__ __launch_bounds__(256) void mma_gemm_pv(float* __restrict__ Cout)
{
    extern __shared__ char smem[];
    const uint32_t sb = smem_u32(smem);
    const int tid  = threadIdx.x;
    const int lane = tid & 31, wid = tid >> 5;
    const int warp_m = wid & 1, warp_n = wid >> 1;
    const int z  = blockIdx.z;
    const int m0 = blockIdx.y * 128, n0 = blockIdx.x * 128;

    const __half* pP  = g_ph  + (size_t)z * SEQ * SEQ;
    const __half* pVh = g_vth + (size_t)z * DIM * SEQ;
    const __half* pVl = g_vtl + (size_t)z * DIM * SEQ;

    const int c1 = tid + 256;
    const int ar0 = tid >> 2, ak0 = (tid & 3) * 8;
    const int ar1 = c1 >> 2,  ak1 = (c1 & 3) * 8;
    const size_t gA0 = (size_t)(m0 + ar0) * SEQ + ak0;
    const size_t gA1 = (size_t)(m0 + ar1) * SEQ + ak1;
    const size_t gB0 = (size_t)(n0 + ar0) * SEQ + ak0;
    const size_t gB1 = (size_t)(n0 + ar1) * SEQ + ak1;
    const uint32_t s0 = (uint32_t)(ar0 * MSTRIDE + ak0) * 2;
    const uint32_t s1 = (uint32_t)(ar1 * MSTRIDE + ak1) * 2;

    float acc[4][4][4];
#pragma unroll
    for (int mi = 0; mi < 4; mi++)
#pragma unroll
        for (int ni = 0; ni < 4; ni++)
#pragma unroll
            for (int rr = 0; rr < 4; rr++) acc[mi][ni][rr] = 0.f;

    uint4 rg[6];
    const int T = SEQ >> 5;

#define PLOADG(K0) do {                                                \
        rg[0] = *(const uint4*)(pP  + gA0 + (K0));                     \
        rg[1] = *(const uint4*)(pP  + gA1 + (K0));                     \
        rg[2] = *(const uint4*)(pVh + gB0 + (K0));                     \
        rg[3] = *(const uint4*)(pVh + gB1 + (K0));                     \
        rg[4] = *(const uint4*)(pVl + gB0 + (K0));                     \
        rg[5] = *(const uint4*)(pVl + gB1 + (K0));                     \
    } while (0)

#define PSTORES(S) do {                                                \
        char* base = smem + (S) * 3 * TILE_B;                          \
        *(uint4*)(base + s0)              = rg[0];                     \
        *(uint4*)(base + s1)              = rg[1];                     \
        *(uint4*)(base + TILE_B + s0)     = rg[2];                     \
        *(uint4*)(base + TILE_B + s1)     = rg[3];                     \
        *(uint4*)(base + 2 * TILE_B + s0) = rg[4];                     \
        *(uint4*)(base + 2 * TILE_B + s1) = rg[5];                     \
    } while (0)

    const int arow = warp_m * 64 + (lane & 15);
    const int acol = (lane >> 4) * 8;
    const int brow = warp_n * 32 + (lane & 7);
    const int bcol = ((lane >> 3) & 1) * 8;

    PLOADG(0);
    PSTORES(0);
    __syncthreads();

    for (int t = 0; t < T; t++) {
        if (t + 1 < T) PLOADG((t + 1) << 5);
        uint32_t base = sb + (uint32_t)(t & 1) * 3 * TILE_B;
#pragma unroll
        for (int kk = 0; kk < 32; kk += 16) {
            uint32_t ah[4][4], bh[4][2], bl[4][2];
#pragma unroll
            for (int mi = 0; mi < 4; mi++) {
                uint32_t ad = (uint32_t)(((arow + mi * 16) * MSTRIDE + kk + acol) * 2);
                ldmx4(ah[mi], base + ad);
            }
#pragma unroll
            for (int ni = 0; ni < 4; ni++) {
                uint32_t bd = (uint32_t)(((brow + ni * 8) * MSTRIDE + kk + bcol) * 2);
                ldmx2(bh[ni], base + TILE_B + bd);
                ldmx2(bl[ni], base + 2 * TILE_B + bd);
            }
#pragma unroll
            for (int mi = 0; mi < 4; mi++)
#pragma unroll
                for (int ni = 0; ni < 4; ni++) {
                    mma_f16(acc[mi][ni], ah[mi], bh[ni]);
                    mma_f16(acc[mi][ni], ah[mi], bl[ni]);
                }
        }
        if (t + 1 < T) {
            PSTORES((t + 1) & 1);
            __syncthreads();
        }
    }
#undef PLOADG
#undef PSTORES

    float* C = Cout + (size_t)z * SEQ * DIM;
#pragma unroll
    for (int mi = 0; mi < 4; mi++) {
        int rowl = warp_m * 64 + mi * 16 + (lane >> 2);
        float inv0 = g_inv[z * SEQ + m0 + rowl];
        float inv1 = g_inv[z * SEQ + m0 + rowl + 8];
#pragma unroll
        for (int ni = 0; ni < 4; ni++) {
            int col = n0 + warp_n * 32 + ni * 8 + (lane & 3) * 2;
            *(float2*)&C[(size_t)(m0 + rowl) * DIM + col] =
                make_float2(acc[mi][ni][0] * inv0, acc[mi][ni][1] * inv0);
            *(float2*)&C[(size_t)(m0 + rowl + 8) * DIM + col] =
                make_float2(acc[mi][ni][2] * inv1, acc[mi][ni][3] * inv1);
        }
    }
}

// ======================= launch =============================================
extern "C" void kernel_launch(void* const* d_in, const int* in_sizes, int n_in,
                              void* d_out, int out_size)
{
    const float* x     = (const float*)d_in[0];
    const float* basis = (const float*)d_in[1];
    const float* Wq    = (const float*)d_in[2];
    const float* bq    = (const float*)d_in[3];
    const float* Wk    = (const float*)d_in[4];
    const float* bk    = (const float*)d_in[5];
    const float* Wv    = (const float*)d_in[6];
    const float* bv    = (const float*)d_in[7];
    float* out = (float*)d_out;

    __nv_bfloat16 *pxh, *pxl, *pwh, *pwl;
    cudaGetSymbolAddress((void**)&pxh, g_xh);
    cudaGetSymbolAddress((void**)&pxl, g_xl);
    cudaGetSymbolAddress((void**)&pwh, g_wh);
    cudaGetSymbolAddress((void**)&pwl, g_wl);

    cudaFuncSetAttribute(mma_gemm_xw, cudaFuncAttributeMaxDynamicSharedMemorySize, MM_SMEM);
    cudaFuncSetAttribute(mma_gemm_pv, cudaFuncAttributeMaxDynamicSharedMemorySize, PV_SMEM);

    // splits
    split_kernel<<<MTOK * DIM / 4 / 256, 256>>>(x, pxh, pxl);
    split_kernel<<<DIM * DIM / 4 / 256, 256>>>(Wv, pwh, pwl);

    // fold (bf16-split C + biases + maxk reset)
    fold_kernel<<<dim3(4, 32), 256>>>(basis, Wq, bq, Wk, bk);

    // kan via mma.sync (64-row tiles, double-buffered) + per-batch key max
    kan_mma_kernel<<<MTOK / 64, 128>>>();
    knorm_kernel<<<MTOK / 256, 256>>>();

    // K3: v = x @ Wv^T + bv  -> vT (fp16 split)
    mma_gemm_xw<<<dim3(DIM / 128, MTOK / 128, 1), 256, MM_SMEM>>>(bv);

    // K4: fused scores + softmax (unnormalized exp fp16 + 1/sum)
    attn_kernel<<<MTOK / 64, 256>>>();

    // K5: out = (P @ v) * inv_sum   (fp16 2-product)
    mma_gemm_pv<<<dim3(DIM / 128, SEQ / 128, NB), 256, PV_SMEM>>>(out);
}

// round 12
// speedup vs baseline: 2.5530x; 1.6065x over previous
#include <cuda_runtime.h>
#include <cuda_fp16.h>
#include <math.h>
#include <stdint.h>

#define DIM   1024
#define NUM_F 16
#define NB    4
#define SEQ   2048
#define MTOK  (NB * SEQ)   // 8192

// ======================= scratch (static device globals) ====================
__device__ __half  g_ph[MTOK * SEQ];      // unnormalized exp(scores), fp16
__device__ float   g_inv[MTOK];           // per-row 1/sum
__device__ __half  g_xf[MTOK * DIM];      // x fp16
__device__ __half  g_wf[DIM * DIM];       // Wv fp16
__device__ __half  g_vt[MTOK * DIM];      // v^T [NB][DIM][SEQ] fp16
__device__ float g_kanq[MTOK * NUM_F];
__device__ float g_kank[MTOK * NUM_F];
__device__ __half g_Cf[32 * DIM];         // folded C (rows 0-15 q, 16-31 k) fp16
__device__ float g_cq[NUM_F];
__device__ float g_ck[NUM_F];
__device__ unsigned g_maxk_bits[NB];      // max |k|^2 per batch (fp32 bits)

// ======================= helpers ============================================
__device__ __forceinline__ uint32_t smem_u32(const void* p) {
    uint32_t a;
    asm("{ .reg .u64 t; cvta.to.shared.u64 t, %1; cvt.u32.u64 %0, t; }"
        : "=r"(a) : "l"(p));
    return a;
}
__device__ __forceinline__ void ldmx4(uint32_t* r, uint32_t addr) {
    asm volatile("ldmatrix.sync.aligned.m8n8.x4.shared.b16 {%0,%1,%2,%3}, [%4];"
        : "=r"(r[0]), "=r"(r[1]), "=r"(r[2]), "=r"(r[3]) : "r"(addr));
}
__device__ __forceinline__ void ldmx2(uint32_t* r, uint32_t addr) {
    asm volatile("ldmatrix.sync.aligned.m8n8.x2.shared.b16 {%0,%1}, [%2];"
        : "=r"(r[0]), "=r"(r[1]) : "r"(addr));
}
__device__ __forceinline__ void mma_f16(float* c, const uint32_t* a, const uint32_t* b) {
    asm volatile("mma.sync.aligned.m16n8k16.row.col.f32.f16.f16.f32 "
        "{%0,%1,%2,%3}, {%4,%5,%6,%7}, {%8,%9}, {%0,%1,%2,%3};"
        : "+f"(c[0]), "+f"(c[1]), "+f"(c[2]), "+f"(c[3])
        : "r"(a[0]), "r"(a[1]), "r"(a[2]), "r"(a[3]), "r"(b[0]), "r"(b[1]));
}
__device__ __forceinline__ uint32_t pack2hf(float a, float b) {
    __half2 t = __floats2half2_rn(a, b);
    return *(uint32_t*)&t;
}
// exp via FMA pipe (no MUFU): exp(x) = 2^(x*log2e), degree-6 poly on frac.
__device__ __forceinline__ float fexp(float x) {
    float t = fmaxf(x * 1.4426950408889634f, -120.f);
    float fl = floorf(t);
    float f = t - fl;
    float p = 1.5403530e-4f;
    p = fmaf(p, f, 1.3333558e-3f);
    p = fmaf(p, f, 9.6181291e-3f);
    p = fmaf(p, f, 5.5504109e-2f);
    p = fmaf(p, f, 2.4022651e-1f);
    p = fmaf(p, f, 6.9314718e-1f);
    p = fmaf(p, f, 1.0f);
    int i = (int)fl;
    return p * __int_as_float((uint32_t)(i + 127) << 23);
}

// ======================= K1: fold basis into Wq/Wk (fp16 out) ===============
__global__ void fold_kernel(const float* __restrict__ basis,
                            const float* __restrict__ Wq, const float* __restrict__ bq,
                            const float* __restrict__ Wk, const float* __restrict__ bk)
{
    if (blockIdx.x == 0 && blockIdx.y == 0 && threadIdx.x < NB)
        g_maxk_bits[threadIdx.x] = 0u;           // reset per call (deterministic)
    int d = blockIdx.x * blockDim.x + threadIdx.x;
    int f = blockIdx.y;
    const float* W  = (f < 16) ? Wq : Wk;
    const float* br = basis + (size_t)(f & 15) * DIM;
    float a = 0.f;
    for (int e = 0; e < DIM; e++)
        a = fmaf(br[e], W[(size_t)e * DIM + d], a);
    g_Cf[f * DIM + d] = __float2half(a);
    if (blockIdx.x == 0 && threadIdx.x == 0) {
        const float* bb = (f < 16) ? bq : bk;
        float s = 0.f;
        for (int e = 0; e < DIM; e++) s = fmaf(br[e], bb[e], s);
        if (f < 16) g_cq[f] = s; else g_ck[f - 16] = s;
    }
}

// ======================= fp32 -> fp16 conversion ============================
__global__ void tohalf_kernel(const float* __restrict__ src, __half* __restrict__ dst)
{
    int i = blockIdx.x * blockDim.x + threadIdx.x;
    float4 v = ((const float4*)src)[i];
    ((uint2*)dst)[i] = make_uint2(pack2hf(v.x, v.y), pack2hf(v.z, v.w));
}

// ======================= K2: kan via mma.sync  [8192,32] = x @ C^T (fp16) ===
#define KSTR 40
__global__ __launch_bounds__(128) void kan_mma_kernel()
{
    __shared__ __align__(16) __half sX[2][64 * KSTR];
    __shared__ __align__(16) __half sC[2][32 * KSTR];
    const int tid = threadIdx.x;
    const int lane = tid & 31, wid = tid >> 5;
    const int m0 = blockIdx.x * 64;

    const int xc1 = tid + 128;
    const int xr0 = tid >> 2, xk0 = (tid & 3) * 8;
    const int xr1 = xc1 >> 2, xk1 = (xc1 & 3) * 8;
    const uint32_t xs0 = (uint32_t)(xr0 * KSTR + xk0) * 2;
    const uint32_t xs1 = (uint32_t)(xr1 * KSTR + xk1) * 2;
    const int cr = tid >> 2, ck = (tid & 3) * 8;
    const uint32_t cs = (uint32_t)(cr * KSTR + ck) * 2;

    float acc[4][4];
#pragma unroll
    for (int ni = 0; ni < 4; ni++)
#pragma unroll
        for (int rr = 0; rr < 4; rr++) acc[ni][rr] = 0.f;

    const int arow = wid * 16 + (lane & 15);
    const int acol = (lane >> 4) * 8;
    const int brow = lane & 7;
    const int bcol = ((lane >> 3) & 1) * 8;

    uint4 r0v, r1v, r2v;
#define KLOAD(K0) do {                                                            \
        r0v = *(const uint4*)(g_xf + (size_t)(m0 + xr0) * DIM + (K0) + xk0);      \
        r1v = *(const uint4*)(g_xf + (size_t)(m0 + xr1) * DIM + (K0) + xk1);      \
        r2v = *(const uint4*)(g_Cf + (size_t)cr * DIM + (K0) + ck);               \
    } while (0)
#define KSTORE(S) do {                                                            \
        *(uint4*)((char*)sX[S] + xs0) = r0v;                                      \
        *(uint4*)((char*)sX[S] + xs1) = r1v;                                      \
        *(uint4*)((char*)sC[S] + cs)  = r2v;                                      \
    } while (0)

    KLOAD(0);
    KSTORE(0);
    __syncthreads();

    const int T = DIM / 32;
    for (int t = 0; t < T; t++) {
        if (t + 1 < T) KLOAD((t + 1) * 32);
        const uint32_t uX = smem_u32(sX[t & 1]);
        const uint32_t uC = smem_u32(sC[t & 1]);
#pragma unroll
        for (int kk = 0; kk < 32; kk += 16) {
            uint32_t ah[4], bh[4][2];
            uint32_t ad = (uint32_t)((arow * KSTR + kk + acol) * 2);
            ldmx4(ah, uX + ad);
#pragma unroll
            for (int ni = 0; ni < 4; ni++) {
                uint32_t bd = (uint32_t)(((brow + ni * 8) * KSTR + kk + bcol) * 2);
                ldmx2(bh[ni], uC + bd);
            }
#pragma unroll
            for (int ni = 0; ni < 4; ni++)
                mma_f16(acc[ni], ah, bh[ni]);
        }
        if (t + 1 < T) {
            __syncthreads();
            KSTORE((t + 1) & 1);
            __syncthreads();
        }
    }
#undef KLOAD
#undef KSTORE

    int r0 = m0 + wid * 16 + (lane >> 2);
#pragma unroll
    for (int ni = 0; ni < 4; ni++) {
        int col = ni * 8 + (lane & 3) * 2;
#pragma unroll
        for (int cdx = 0; cdx < 2; cdx++) {
            int c = col + cdx;
            float bias = (c < 16) ? g_cq[c] : g_ck[c - 16];
            float* dst = (c < 16) ? g_kanq : g_kank;
            int f = c & 15;
            dst[(size_t)r0 * NUM_F + f]       = acc[ni][cdx]     + bias;
            dst[(size_t)(r0 + 8) * NUM_F + f] = acc[ni][cdx + 2] + bias;
        }
    }
}

// ======================= K2b: per-batch max |k|^2 ===========================
__global__ void knorm_kernel()
{
    int r = blockIdx.x * 256 + threadIdx.x;   // 0..8191
    const float4* kr = (const float4*)(g_kank + (size_t)r * NUM_F);
    float s = 0.f;
#pragma unroll
    for (int i = 0; i < 4; i++) {
        float4 v = kr[i];
        s += v.x * v.x + v.y * v.y + v.z * v.z + v.w * v.w;
    }
#pragma unroll
    for (int off = 16; off; off >>= 1)
        s = fmaxf(s, __shfl_xor_sync(0xffffffffu, s, off));
    if ((threadIdx.x & 31) == 0)
        atomicMax(&g_maxk_bits[r >> 11], __float_as_uint(s));
}

// ======================= K4: fused scores + softmax (single pass) ===========
#define ACH 256
__global__ __launch_bounds__(256) void attn_kernel()
{
    __shared__ __align__(16) float sK[ACH][20];
    const int tid = threadIdx.x;
    const int lane = tid & 31, wid = tid >> 5;
    const int blk = blockIdx.x;          // 128 blocks, 64 rows each
    const int b = blk >> 5;
    const int r0 = (blk & 31) * 64;
    const float maxk = sqrtf(__uint_as_float(g_maxk_bits[b]));
    const float inv32 = 1.0f / 32.0f;

    for (int p = 0; p < 2; p++) {
        const int rbase = r0 + wid * 8 + p * 4;
        float q[4][16], bound[4], sum[4];
#pragma unroll
        for (int i = 0; i < 4; i++) {
            const float* qr = g_kanq + (size_t)(b * SEQ + rbase + i) * NUM_F;
            float qs = 0.f;
#pragma unroll
            for (int f = 0; f < 16; f++) { q[i][f] = qr[f]; qs = fmaf(qr[f], qr[f], qs); }
            bound[i] = sqrtf(qs) * maxk;
            sum[i] = 0.f;
        }

        for (int c = 0; c < SEQ / ACH; c++) {
            __syncthreads();
#pragma unroll
            for (int u = 0; u < 4; u++) {
                int e4 = tid + u * 256;
                int kr = e4 >> 2, kf = (e4 & 3) * 4;
                *(float4*)&sK[kr][kf] =
                    *(const float4*)(g_kank + (size_t)(b * SEQ + c * ACH + kr) * NUM_F + kf);
            }
            __syncthreads();
#pragma unroll 2
            for (int kg = 0; kg < ACH / 32; kg++) {
                int jj = kg * 32 + lane;
                float k[16];
                *(float4*)&k[0]  = *(const float4*)&sK[jj][0];
                *(float4*)&k[4]  = *(const float4*)&sK[jj][4];
                *(float4*)&k[8]  = *(const float4*)&sK[jj][8];
                *(float4*)&k[12] = *(const float4*)&sK[jj][12];
                size_t jbase = (size_t)(b * SEQ) * SEQ + (size_t)c * ACH + jj;
#pragma unroll
                for (int i = 0; i < 4; i++) {
                    float s = 0.f;
#pragma unroll
                    for (int f = 0; f < 16; f++) s = fmaf(q[i][f], k[f], s);
                    float e = fexp((s - bound[i]) * inv32);
                    sum[i] += e;
                    g_ph[jbase + (size_t)(rbase + i) * SEQ] = __float2half(e);
                }
            }
        }
#pragma unroll
        for (int i = 0; i < 4; i++) {
#pragma unroll
            for (int off = 16; off; off >>= 1)
                sum[i] += __shfl_xor_sync(0xffffffffu, sum[i], off);
            if (lane == 0) g_inv[b * SEQ + rbase + i] = 1.0f / sum[i];
        }
        __syncthreads();
    }
}

// ======================= generic single-fp16 GEMM core ======================
// Block 128x128, 8 warps each 64x32, BK=32, double-buffered LDG->reg->STS.
// 2 smem tiles per stage (A, B).
#define MSTRIDE 40
#define TILE_B  (128 * MSTRIDE * 2)     // 10240 B
#define XW_SMEM 67584                   // max(4*TILE_B, 128*132*4 epi buffer)
#define PV_SMEM (4 * TILE_B)            // 40960 B

// K3: v = x @ Wv^T + bv -> vT fp16
__global__ __launch_bounds__(256, 1) void mma_gemm_xw(const float* __restrict__ bias)
{
    extern __shared__ char smem[];
    const uint32_t sb = smem_u32(smem);
    const int tid  = threadIdx.x;
    const int lane = tid & 31, wid = tid >> 5;
    const int warp_m = wid & 1, warp_n = wid >> 1;
    const int m0 = blockIdx.y * 128, n0 = blockIdx.x * 128;

    const int c1 = tid + 256;
    const int ar0 = tid >> 2, ak0 = (tid & 3) * 8;
    const int ar1 = c1 >> 2,  ak1 = (c1 & 3) * 8;
    const size_t gA0 = (size_t)(m0 + ar0) * DIM + ak0;
    const size_t gA1 = (size_t)(m0 + ar1) * DIM + ak1;
    const size_t gB0 = (size_t)(n0 + ar0) * DIM + ak0;
    const size_t gB1 = (size_t)(n0 + ar1) * DIM + ak1;
    const uint32_t s0 = (uint32_t)(ar0 * MSTRIDE + ak0) * 2;
    const uint32_t s1 = (uint32_t)(ar1 * MSTRIDE + ak1) * 2;

    float acc[4][4][4];
#pragma unroll
    for (int mi = 0; mi < 4; mi++)
#pragma unroll
        for (int ni = 0; ni < 4; ni++)
#pragma unroll
            for (int rr = 0; rr < 4; rr++) acc[mi][ni][rr] = 0.f;

    uint4 rg[4];
    const int T = DIM >> 5;

#define LOADG(K0) do {                                                 \
        rg[0] = *(const uint4*)(g_xf + gA0 + (K0));                    \
        rg[1] = *(const uint4*)(g_xf + gA1 + (K0));                    \
        rg[2] = *(const uint4*)(g_wf + gB0 + (K0));                    \
        rg[3] = *(const uint4*)(g_wf + gB1 + (K0));                    \
    } while (0)
#define STORES(S) do {                                                 \
        char* base = smem + (S) * 2 * TILE_B;                          \
        *(uint4*)(base + s0)          = rg[0];                         \
        *(uint4*)(base + s1)          = rg[1];                         \
        *(uint4*)(base + TILE_B + s0) = rg[2];                         \
        *(uint4*)(base + TILE_B + s1) = rg[3];                         \
    } while (0)

    const int arow = warp_m * 64 + (lane & 15);
    const int acol = (lane >> 4) * 8;
    const int brow = warp_n * 32 + (lane & 7);
    const int bcol = ((lane >> 3) & 1) * 8;

    LOADG(0);
    STORES(0);
    __syncthreads();

    for (int t = 0; t < T; t++) {
        if (t + 1 < T) LOADG((t + 1) << 5);
        uint32_t base = sb + (uint32_t)(t & 1) * 2 * TILE_B;
#pragma unroll
        for (int kk = 0; kk < 32; kk += 16) {
            uint32_t ah[4][4], bh[4][2];
#pragma unroll
            for (int mi = 0; mi < 4; mi++) {
                uint32_t ad = (uint32_t)(((arow + mi * 16) * MSTRIDE + kk + acol) * 2);
                ldmx4(ah[mi], base + ad);
            }
#pragma unroll
            for (int ni = 0; ni < 4; ni++) {
                uint32_t bd = (uint32_t)(((brow + ni * 8) * MSTRIDE + kk + bcol) * 2);
                ldmx2(bh[ni], base + TILE_B + bd);
            }
#pragma unroll
            for (int mi = 0; mi < 4; mi++)
#pragma unroll
                for (int ni = 0; ni < 4; ni++)
                    mma_f16(acc[mi][ni], ah[mi], bh[ni]);
        }
        if (t + 1 < T) {
            STORES((t + 1) & 1);
            __syncthreads();
        }
    }
#undef LOADG
#undef STORES

    // epilogue: add bias, transpose in smem, write fp16 vT
    __syncthreads();
    float* st = (float*)smem;        // [128 n][132]
#pragma unroll
    for (int mi = 0; mi < 4; mi++) {
        int rowl = warp_m * 64 + mi * 16 + (lane >> 2);
#pragma unroll
        for (int ni = 0; ni < 4; ni++) {
            int coll = warp_n * 32 + ni * 8 + (lane & 3) * 2;
            float b0 = bias[n0 + coll], b1 = bias[n0 + coll + 1];
            st[coll * 132 + rowl]           = acc[mi][ni][0] + b0;
            st[(coll + 1) * 132 + rowl]     = acc[mi][ni][1] + b1;
            st[coll * 132 + rowl + 8]       = acc[mi][ni][2] + b0;
            st[(coll + 1) * 132 + rowl + 8] = acc[mi][ni][3] + b1;
        }
    }
    __syncthreads();
    int bz  = m0 >> 11;
    int m0s = m0 & (SEQ - 1);
    for (int w = tid; w < 128 * 64; w += 256) {
        int d = w >> 6, mp = w & 63;
        float v0 = st[d * 132 + mp * 2];
        float v1 = st[d * 132 + mp * 2 + 1];
        size_t idx = (((size_t)(bz * DIM + n0 + d) * SEQ + m0s) >> 1) + mp;
        ((uint32_t*)g_vt)[idx] = pack2hf(v0, v1);
    }
}

// K5: out = (P @ v) * inv_sum   (single product)
__global__ __launch_bounds__(256) void mma_gemm_pv(float* __restrict__ Cout)
{
    extern __shared__ char smem[];
    const uint32_t sb = smem_u32(smem);
    const int tid  = threadIdx.x;
    const int lane = tid & 31, wid = tid >> 5;
    const int warp_m = wid & 1, warp_n = wid >> 1;
    const int z  = blockIdx.z;
    const int m0 = blockIdx.y * 128, n0 = blockIdx.x * 128;

    const __half* pP = g_ph + (size_t)z * SEQ * SEQ;
    const __half* pV = g_vt + (size_t)z * DIM * SEQ;

    const int c1 = tid + 256;
    const int ar0 = tid >> 2, ak0 = (tid & 3) * 8;
    const int ar1 = c1 >> 2,  ak1 = (c1 & 3) * 8;
    const size_t gA0 = (size_t)(m0 + ar0) * SEQ + ak0;
    const size_t gA1 = (size_t)(m0 + ar1) * SEQ + ak1;
    const size_t gB0 = (size_t)(n0 + ar0) * SEQ + ak0;
    const size_t gB1 = (size_t)(n0 + ar1) * SEQ + ak1;
    const uint32_t s0 = (uint32_t)(ar0 * MSTRIDE + ak0) * 2;
    const uint32_t s1 = (uint32_t)(ar1 * MSTRIDE + ak1) * 2;

    float acc[4][4][4];
#pragma unroll
    for (int mi = 0; mi < 4; mi++)
#pragma unroll
        for (int ni = 0; ni < 4; ni++)
#pragma unroll
            for (int rr = 0; rr < 4; rr++) acc[mi][ni][rr] = 0.f;

    uint4 rg[4];
    const int T = SEQ >> 5;

#define PLOADG(K0) do {                                                \
        rg[0] = *(const uint4*)(pP + gA0 + (K0));                      \
        rg[1] = *(const uint4*)(pP + gA1 + (K0));                      \
        rg[2] = *(const uint4*)(pV + gB0 + (K0));                      \
        rg[3] = *(const uint4*)(pV + gB1 + (K0));                      \
    } while (0)
#define PSTORES(S) do {                                                \
        char* base = smem + (S) * 2 * TILE_B;                          \
        *(uint4*)(base + s0)          = rg[0];                         \
        *(uint4*)(base + s1)          = rg[1];                         \
        *(uint4*)(base + TILE_B + s0) = rg[2];                         \
        *(uint4*)(base + TILE_B + s1) = rg[3];                         \
    } while (0)

    const int arow = warp_m * 64 + (lane & 15);
    const int acol = (lane >> 4) * 8;
    const int brow = warp_n * 32 + (lane & 7);
    const int bcol = ((lane >> 3) & 1) * 8;

    PLOADG(0);
    PSTORES(0);
    __syncthreads();

    for (int t = 0; t < T; t++) {
        if (t + 1 < T) PLOADG((t + 1) << 5);
        uint32_t base = sb + (uint32_t)(t & 1) * 2 * TILE_B;
#pragma unroll
        for (int kk = 0; kk < 32; kk += 16) {
            uint32_t ah[4][4], bh[4][2];
#pragma unroll
            for (int mi = 0; mi < 4; mi++) {
                uint32_t ad = (uint32_t)(((arow + mi * 16) * MSTRIDE + kk + acol) * 2);
                ldmx4(ah[mi], base + ad);
            }
#pragma unroll
            for (int ni = 0; ni < 4; ni++) {
                uint32_t bd = (uint32_t)(((brow + ni * 8) * MSTRIDE + kk + bcol) * 2);
                ldmx2(bh[ni], base + TILE_B + bd);
            }
#pragma unroll
            for (int mi = 0; mi < 4; mi++)
#pragma unroll
                for (int ni = 0; ni < 4; ni++)
                    mma_f16(acc[mi][ni], ah[mi], bh[ni]);
        }
        if (t + 1 < T) {
            PSTORES((t + 1) & 1);
            __syncthreads();
        }
    }
#undef PLOADG
#undef PSTORES

    float* C = Cout + (size_t)z * SEQ * DIM;
#pragma unroll
    for (int mi = 0; mi < 4; mi++) {
        int rowl = warp_m * 64 + mi * 16 + (lane >> 2);
        float inv0 = g_inv[z * SEQ + m0 + rowl];
        float inv1 = g_inv[z * SEQ + m0 + rowl + 8];
#pragma unroll
        for (int ni = 0; ni < 4; ni++) {
            int col = n0 + warp_n * 32 + ni * 8 + (lane & 3) * 2;
            *(float2*)&C[(size_t)(m0 + rowl) * DIM + col] =
                make_float2(acc[mi][ni][0] * inv0, acc[mi][ni][1] * inv0);
            *(float2*)&C[(size_t)(m0 + rowl + 8) * DIM + col] =
                make_float2(acc[mi][ni][2] * inv1, acc[mi][ni][3] * inv1);
        }
    }
}

// ======================= launch =============================================
extern "C" void kernel_launch(void* const* d_in, const int* in_sizes, int n_in,
                              void* d_out, int out_size)
{
    const float* x     = (const float*)d_in[0];
    const float* basis = (const float*)d_in[1];
    const float* Wq    = (const float*)d_in[2];
    const float* bq    = (const float*)d_in[3];
    const float* Wk    = (const float*)d_in[4];
    const float* bk    = (const float*)d_in[5];
    const float* Wv    = (const float*)d_in[6];
    const float* bv    = (const float*)d_in[7];
    float* out = (float*)d_out;

    __half *pxf, *pwf;
    cudaGetSymbolAddress((void**)&pxf, g_xf);
    cudaGetSymbolAddress((void**)&pwf, g_wf);

    cudaFuncSetAttribute(mma_gemm_xw, cudaFuncAttributeMaxDynamicSharedMemorySize, XW_SMEM);
    cudaFuncSetAttribute(mma_gemm_pv, cudaFuncAttributeMaxDynamicSharedMemorySize, PV_SMEM);

    // fp16 conversions
    tohalf_kernel<<<MTOK * DIM / 4 / 256, 256>>>(x, pxf);
    tohalf_kernel<<<DIM * DIM / 4 / 256, 256>>>(Wv, pwf);

    // fold (fp16 C + biases + maxk reset)
    fold_kernel<<<dim3(4, 32), 256>>>(basis, Wq, bq, Wk, bk);

    // kan via mma.sync (fp16 single-product) + per-batch key max
    kan_mma_kernel<<<MTOK / 64, 128>>>();
    knorm_kernel<<<MTOK / 256, 256>>>();

    // K3: v = x @ Wv^T + bv  -> vT fp16 (single product)
    mma_gemm_xw<<<dim3(DIM / 128, MTOK / 128, 1), 256, XW_SMEM>>>(bv);

    // K4: fused scores + softmax (unnormalized exp fp16 + 1/sum)
    attn_kernel<<<MTOK / 64, 256>>>();

    // K5: out = (P @ v) * inv_sum  (single product)
    mma_gemm_pv<<<dim3(DIM / 128, SEQ / 128, NB), 256, PV_SMEM>>>(out);
}

// round 13
// speedup vs baseline: 2.6074x; 1.0213x over previous
#include <cuda_runtime.h>
#include <cuda_fp16.h>
#include <math.h>
#include <stdint.h>

#define DIM   1024
#define NUM_F 16
#define NB    4
#define SEQ   2048
#define MTOK  (NB * SEQ)   // 8192

// ======================= scratch (static device globals) ====================
__device__ __half  g_ph[MTOK * SEQ];      // unnormalized exp(scores), fp16
__device__ float   g_inv[MTOK];           // per-row 1/sum
__device__ __half  g_xf[MTOK * DIM];      // x fp16
__device__ __half  g_wf[DIM * DIM];       // Wv fp16
__device__ __half  g_vt[MTOK * DIM];      // v^T [NB][DIM][SEQ] fp16
__device__ float g_kanq[MTOK * NUM_F];
__device__ float g_kank[MTOK * NUM_F];
__device__ __half g_Cf[32 * DIM];         // folded C (rows 0-15 q, 16-31 k) fp16
__device__ float g_cq[NUM_F];
__device__ float g_ck[NUM_F];
__device__ unsigned g_maxk_bits[NB];      // max |k|^2 per batch (fp32 bits)

// ======================= helpers ============================================
__device__ __forceinline__ uint32_t smem_u32(const void* p) {
    uint32_t a;
    asm("{ .reg .u64 t; cvta.to.shared.u64 t, %1; cvt.u32.u64 %0, t; }"
        : "=r"(a) : "l"(p));
    return a;
}
__device__ __forceinline__ void ldmx4(uint32_t* r, uint32_t addr) {
    asm volatile("ldmatrix.sync.aligned.m8n8.x4.shared.b16 {%0,%1,%2,%3}, [%4];"
        : "=r"(r[0]), "=r"(r[1]), "=r"(r[2]), "=r"(r[3]) : "r"(addr));
}
__device__ __forceinline__ void ldmx2(uint32_t* r, uint32_t addr) {
    asm volatile("ldmatrix.sync.aligned.m8n8.x2.shared.b16 {%0,%1}, [%2];"
        : "=r"(r[0]), "=r"(r[1]) : "r"(addr));
}
__device__ __forceinline__ void mma_f16(float* c, const uint32_t* a, const uint32_t* b) {
    asm volatile("mma.sync.aligned.m16n8k16.row.col.f32.f16.f16.f32 "
        "{%0,%1,%2,%3}, {%4,%5,%6,%7}, {%8,%9}, {%0,%1,%2,%3};"
        : "+f"(c[0]), "+f"(c[1]), "+f"(c[2]), "+f"(c[3])
        : "r"(a[0]), "r"(a[1]), "r"(a[2]), "r"(a[3]), "r"(b[0]), "r"(b[1]));
}
__device__ __forceinline__ uint32_t pack2hf(float a, float b) {
    __half2 t = __floats2half2_rn(a, b);
    return *(uint32_t*)&t;
}
// exp via FMA pipe (no MUFU): exp(x) = 2^(x*log2e), degree-6 poly on frac.
__device__ __forceinline__ float fexp(float x) {
    float t = fmaxf(x * 1.4426950408889634f, -120.f);
    float fl = floorf(t);
    float f = t - fl;
    float p = 1.5403530e-4f;
    p = fmaf(p, f, 1.3333558e-3f);
    p = fmaf(p, f, 9.6181291e-3f);
    p = fmaf(p, f, 5.5504109e-2f);
    p = fmaf(p, f, 2.4022651e-1f);
    p = fmaf(p, f, 6.9314718e-1f);
    p = fmaf(p, f, 1.0f);
    int i = (int)fl;
    return p * __int_as_float((uint32_t)(i + 127) << 23);
}

// ======================= K1: fold basis into Wq/Wk (fp16 out) ===============
__global__ void fold_kernel(const float* __restrict__ basis,
                            const float* __restrict__ Wq, const float* __restrict__ bq,
                            const float* __restrict__ Wk, const float* __restrict__ bk)
{
    if (blockIdx.x == 0 && blockIdx.y == 0 && threadIdx.x < NB)
        g_maxk_bits[threadIdx.x] = 0u;           // reset per call (deterministic)
    int d = blockIdx.x * blockDim.x + threadIdx.x;
    int f = blockIdx.y;
    const float* W  = (f < 16) ? Wq : Wk;
    const float* br = basis + (size_t)(f & 15) * DIM;
    float a = 0.f;
    for (int e = 0; e < DIM; e++)
        a = fmaf(br[e], W[(size_t)e * DIM + d], a);
    g_Cf[f * DIM + d] = __float2half(a);
    if (blockIdx.x == 0 && threadIdx.x == 0) {
        const float* bb = (f < 16) ? bq : bk;
        float s = 0.f;
        for (int e = 0; e < DIM; e++) s = fmaf(br[e], bb[e], s);
        if (f < 16) g_cq[f] = s; else g_ck[f - 16] = s;
    }
}

// ======================= fp32 -> fp16 conversion ============================
__global__ void tohalf_kernel(const float* __restrict__ src, __half* __restrict__ dst)
{
    int i = blockIdx.x * blockDim.x + threadIdx.x;
    float4 v = ((const float4*)src)[i];
    ((uint2*)dst)[i] = make_uint2(pack2hf(v.x, v.y), pack2hf(v.z, v.w));
}

// ======================= K2: kan via mma.sync  [8192,32] = x @ C^T (fp16) ===
#define KSTR 40
__global__ __launch_bounds__(128) void kan_mma_kernel()
{
    __shared__ __align__(16) __half sX[2][64 * KSTR];
    __shared__ __align__(16) __half sC[2][32 * KSTR];
    const int tid = threadIdx.x;
    const int lane = tid & 31, wid = tid >> 5;
    const int m0 = blockIdx.x * 64;

    const int xc1 = tid + 128;
    const int xr0 = tid >> 2, xk0 = (tid & 3) * 8;
    const int xr1 = xc1 >> 2, xk1 = (xc1 & 3) * 8;
    const uint32_t xs0 = (uint32_t)(xr0 * KSTR + xk0) * 2;
    const uint32_t xs1 = (uint32_t)(xr1 * KSTR + xk1) * 2;
    const int cr = tid >> 2, ck = (tid & 3) * 8;
    const uint32_t cs = (uint32_t)(cr * KSTR + ck) * 2;

    float acc[4][4];
#pragma unroll
    for (int ni = 0; ni < 4; ni++)
#pragma unroll
        for (int rr = 0; rr < 4; rr++) acc[ni][rr] = 0.f;

    const int arow = wid * 16 + (lane & 15);
    const int acol = (lane >> 4) * 8;
    const int brow = lane & 7;
    const int bcol = ((lane >> 3) & 1) * 8;

    uint4 r0v, r1v, r2v;
#define KLOAD(K0) do {                                                            \
        r0v = *(const uint4*)(g_xf + (size_t)(m0 + xr0) * DIM + (K0) + xk0);      \
        r1v = *(const uint4*)(g_xf + (size_t)(m0 + xr1) * DIM + (K0) + xk1);      \
        r2v = *(const uint4*)(g_Cf + (size_t)cr * DIM + (K0) + ck);               \
    } while (0)
#define KSTORE(S) do {                                                            \
        *(uint4*)((char*)sX[S] + xs0) = r0v;                                      \
        *(uint4*)((char*)sX[S] + xs1) = r1v;                                      \
        *(uint4*)((char*)sC[S] + cs)  = r2v;                                      \
    } while (0)

    KLOAD(0);
    KSTORE(0);
    __syncthreads();

    const int T = DIM / 32;
    for (int t = 0; t < T; t++) {
        if (t + 1 < T) KLOAD((t + 1) * 32);
        const uint32_t uX = smem_u32(sX[t & 1]);
        const uint32_t uC = smem_u32(sC[t & 1]);
#pragma unroll
        for (int kk = 0; kk < 32; kk += 16) {
            uint32_t ah[4], bh[4][2];
            uint32_t ad = (uint32_t)((arow * KSTR + kk + acol) * 2);
            ldmx4(ah, uX + ad);
#pragma unroll
            for (int ni = 0; ni < 4; ni++) {
                uint32_t bd = (uint32_t)(((brow + ni * 8) * KSTR + kk + bcol) * 2);
                ldmx2(bh[ni], uC + bd);
            }
#pragma unroll
            for (int ni = 0; ni < 4; ni++)
                mma_f16(acc[ni], ah, bh[ni]);
        }
        if (t + 1 < T) {
            __syncthreads();
            KSTORE((t + 1) & 1);
            __syncthreads();
        }
    }
#undef KLOAD
#undef KSTORE

    int r0 = m0 + wid * 16 + (lane >> 2);
#pragma unroll
    for (int ni = 0; ni < 4; ni++) {
        int col = ni * 8 + (lane & 3) * 2;
#pragma unroll
        for (int cdx = 0; cdx < 2; cdx++) {
            int c = col + cdx;
            float bias = (c < 16) ? g_cq[c] : g_ck[c - 16];
            float* dst = (c < 16) ? g_kanq : g_kank;
            int f = c & 15;
            dst[(size_t)r0 * NUM_F + f]       = acc[ni][cdx]     + bias;
            dst[(size_t)(r0 + 8) * NUM_F + f] = acc[ni][cdx + 2] + bias;
        }
    }
}

// ======================= K2b: per-batch max |k|^2 ===========================
__global__ void knorm_kernel()
{
    int r = blockIdx.x * 256 + threadIdx.x;   // 0..8191
    const float4* kr = (const float4*)(g_kank + (size_t)r * NUM_F);
    float s = 0.f;
#pragma unroll
    for (int i = 0; i < 4; i++) {
        float4 v = kr[i];
        s += v.x * v.x + v.y * v.y + v.z * v.z + v.w * v.w;
    }
#pragma unroll
    for (int off = 16; off; off >>= 1)
        s = fmaxf(s, __shfl_xor_sync(0xffffffffu, s, off));
    if ((threadIdx.x & 31) == 0)
        atomicMax(&g_maxk_bits[r >> 11], __float_as_uint(s));
}

// ======================= K4: fused scores + softmax (single pass) ===========
#define ACH 256
__global__ __launch_bounds__(256) void attn_kernel()
{
    __shared__ __align__(16) float sK[ACH][20];
    const int tid = threadIdx.x;
    const int lane = tid & 31, wid = tid >> 5;
    const int blk = blockIdx.x;          // 128 blocks, 64 rows each
    const int b = blk >> 5;
    const int r0 = (blk & 31) * 64;
    const float maxk = sqrtf(__uint_as_float(g_maxk_bits[b]));
    const float inv32 = 1.0f / 32.0f;

    for (int p = 0; p < 2; p++) {
        const int rbase = r0 + wid * 8 + p * 4;
        float q[4][16], bound[4], sum[4];
#pragma unroll
        for (int i = 0; i < 4; i++) {
            const float* qr = g_kanq + (size_t)(b * SEQ + rbase + i) * NUM_F;
            float qs = 0.f;
#pragma unroll
            for (int f = 0; f < 16; f++) { q[i][f] = qr[f]; qs = fmaf(qr[f], qr[f], qs); }
            bound[i] = sqrtf(qs) * maxk;
            sum[i] = 0.f;
        }

        for (int c = 0; c < SEQ / ACH; c++) {
            __syncthreads();
#pragma unroll
            for (int u = 0; u < 4; u++) {
                int e4 = tid + u * 256;
                int kr = e4 >> 2, kf = (e4 & 3) * 4;
                *(float4*)&sK[kr][kf] =
                    *(const float4*)(g_kank + (size_t)(b * SEQ + c * ACH + kr) * NUM_F + kf);
            }
            __syncthreads();
#pragma unroll 2
            for (int kg = 0; kg < ACH / 32; kg++) {
                int jj = kg * 32 + lane;
                float k[16];
                *(float4*)&k[0]  = *(const float4*)&sK[jj][0];
                *(float4*)&k[4]  = *(const float4*)&sK[jj][4];
                *(float4*)&k[8]  = *(const float4*)&sK[jj][8];
                *(float4*)&k[12] = *(const float4*)&sK[jj][12];
                size_t jbase = (size_t)(b * SEQ) * SEQ + (size_t)c * ACH + jj;
#pragma unroll
                for (int i = 0; i < 4; i++) {
                    float s = 0.f;
#pragma unroll
                    for (int f = 0; f < 16; f++) s = fmaf(q[i][f], k[f], s);
                    float e = fexp((s - bound[i]) * inv32);
                    sum[i] += e;
                    g_ph[jbase + (size_t)(rbase + i) * SEQ] = __float2half(e);
                }
            }
        }
#pragma unroll
        for (int i = 0; i < 4; i++) {
#pragma unroll
            for (int off = 16; off; off >>= 1)
                sum[i] += __shfl_xor_sync(0xffffffffu, sum[i], off);
            if (lane == 0) g_inv[b * SEQ + rbase + i] = 1.0f / sum[i];
        }
        __syncthreads();
    }
}

// ======================= generic single-fp16 GEMM core ======================
// Block 128x128, 8 warps each 64x32, BK=32, double-buffered LDG->reg->STS.
// 2 smem tiles per stage; 40960 B total -> 2 CTAs/SM for cross-CTA latency hiding.
#define MSTRIDE 40
#define TILE_B  (128 * MSTRIDE * 2)     // 10240 B
#define GM_SMEM (4 * TILE_B)            // 40960 B

// K3: v = x @ Wv^T + bv -> vT fp16 (epilogue reuses first 33 KB of smem)
__global__ __launch_bounds__(256, 2) void mma_gemm_xw(const float* __restrict__ bias)
{
    extern __shared__ char smem[];
    const uint32_t sb = smem_u32(smem);
    const int tid  = threadIdx.x;
    const int lane = tid & 31, wid = tid >> 5;
    const int warp_m = wid & 1, warp_n = wid >> 1;
    const int m0 = blockIdx.y * 128, n0 = blockIdx.x * 128;

    const int c1 = tid + 256;
    const int ar0 = tid >> 2, ak0 = (tid & 3) * 8;
    const int ar1 = c1 >> 2,  ak1 = (c1 & 3) * 8;
    const size_t gA0 = (size_t)(m0 + ar0) * DIM + ak0;
    const size_t gA1 = (size_t)(m0 + ar1) * DIM + ak1;
    const size_t gB0 = (size_t)(n0 + ar0) * DIM + ak0;
    const size_t gB1 = (size_t)(n0 + ar1) * DIM + ak1;
    const uint32_t s0 = (uint32_t)(ar0 * MSTRIDE + ak0) * 2;
    const uint32_t s1 = (uint32_t)(ar1 * MSTRIDE + ak1) * 2;

    float acc[4][4][4];
#pragma unroll
    for (int mi = 0; mi < 4; mi++)
#pragma unroll
        for (int ni = 0; ni < 4; ni++)
#pragma unroll
            for (int rr = 0; rr < 4; rr++) acc[mi][ni][rr] = 0.f;

    uint4 rg[4];
    const int T = DIM >> 5;

#define LOADG(K0) do {                                                 \
        rg[0] = *(const uint4*)(g_xf + gA0 + (K0));                    \
        rg[1] = *(const uint4*)(g_xf + gA1 + (K0));                    \
        rg[2] = *(const uint4*)(g_wf + gB0 + (K0));                    \
        rg[3] = *(const uint4*)(g_wf + gB1 + (K0));                    \
    } while (0)
#define STORES(S) do {                                                 \
        char* base = smem + (S) * 2 * TILE_B;                          \
        *(uint4*)(base + s0)          = rg[0];                         \
        *(uint4*)(base + s1)          = rg[1];                         \
        *(uint4*)(base + TILE_B + s0) = rg[2];                         \
        *(uint4*)(base + TILE_B + s1) = rg[3];                         \
    } while (0)

    const int arow = warp_m * 64 + (lane & 15);
    const int acol = (lane >> 4) * 8;
    const int brow = warp_n * 32 + (lane & 7);
    const int bcol = ((lane >> 3) & 1) * 8;

    LOADG(0);
    STORES(0);
    __syncthreads();

    for (int t = 0; t < T; t++) {
        if (t + 1 < T) LOADG((t + 1) << 5);
        uint32_t base = sb + (uint32_t)(t & 1) * 2 * TILE_B;
#pragma unroll
        for (int kk = 0; kk < 32; kk += 16) {
            uint32_t ah[4][4], bh[4][2];
#pragma unroll
            for (int mi = 0; mi < 4; mi++) {
                uint32_t ad = (uint32_t)(((arow + mi * 16) * MSTRIDE + kk + acol) * 2);
                ldmx4(ah[mi], base + ad);
            }
#pragma unroll
            for (int ni = 0; ni < 4; ni++) {
                uint32_t bd = (uint32_t)(((brow + ni * 8) * MSTRIDE + kk + bcol) * 2);
                ldmx2(bh[ni], base + TILE_B + bd);
            }
#pragma unroll
            for (int mi = 0; mi < 4; mi++)
#pragma unroll
                for (int ni = 0; ni < 4; ni++)
                    mma_f16(acc[mi][ni], ah[mi], bh[ni]);
        }
        if (t + 1 < T) {
            STORES((t + 1) & 1);
            __syncthreads();
        }
    }
#undef LOADG
#undef STORES

    // epilogue: two 64-column halves so buffer [64][132] f32 = 33792 B fits smem
    float* st = (float*)smem;
    int bz  = m0 >> 11;
    int m0s = m0 & (SEQ - 1);
#pragma unroll
    for (int half = 0; half < 2; half++) {
        __syncthreads();
        // warps with warp_n in {2*half, 2*half+1} own columns [half*64, half*64+64)
        if ((warp_n >> 1) == half) {
            int wn = warp_n & 1;   // 0..1 within half
#pragma unroll
            for (int mi = 0; mi < 4; mi++) {
                int rowl = warp_m * 64 + mi * 16 + (lane >> 2);
#pragma unroll
                for (int ni = 0; ni < 4; ni++) {
                    int coll = wn * 32 + ni * 8 + (lane & 3) * 2;   // 0..63
                    int gcol = half * 64 + coll;
                    float b0 = bias[n0 + gcol], b1 = bias[n0 + gcol + 1];
                    st[coll * 132 + rowl]           = acc[mi][ni][0] + b0;
                    st[(coll + 1) * 132 + rowl]     = acc[mi][ni][1] + b1;
                    st[coll * 132 + rowl + 8]       = acc[mi][ni][2] + b0;
                    st[(coll + 1) * 132 + rowl + 8] = acc[mi][ni][3] + b1;
                }
            }
        }
        __syncthreads();
        for (int w = tid; w < 64 * 64; w += 256) {
            int d = w >> 6, mp = w & 63;     // d: local col 0..63, mp: row pair
            float v0 = st[d * 132 + mp * 2];
            float v1 = st[d * 132 + mp * 2 + 1];
            size_t idx = (((size_t)(bz * DIM + n0 + half * 64 + d) * SEQ + m0s) >> 1) + mp;
            ((uint32_t*)g_vt)[idx] = pack2hf(v0, v1);
        }
    }
}

// K5: out = (P @ v) * inv_sum   (single product)
__global__ __launch_bounds__(256, 2) void mma_gemm_pv(float* __restrict__ Cout)
{
    extern __shared__ char smem[];
    const uint32_t sb = smem_u32(smem);
    const int tid  = threadIdx.x;
    const int lane = tid & 31, wid = tid >> 5;
    const int warp_m = wid & 1, warp_n = wid >> 1;
    const int z  = blockIdx.z;
    const int m0 = blockIdx.y * 128, n0 = blockIdx.x * 128;

    const __half* pP = g_ph + (size_t)z * SEQ * SEQ;
    const __half* pV = g_vt + (size_t)z * DIM * SEQ;

    const int c1 = tid + 256;
    const int ar0 = tid >> 2, ak0 = (tid & 3) * 8;
    const int ar1 = c1 >> 2,  ak1 = (c1 & 3) * 8;
    const size_t gA0 = (size_t)(m0 + ar0) * SEQ + ak0;
    const size_t gA1 = (size_t)(m0 + ar1) * SEQ + ak1;
    const size_t gB0 = (size_t)(n0 + ar0) * SEQ + ak0;
    const size_t gB1 = (size_t)(n0 + ar1) * SEQ + ak1;
    const uint32_t s0 = (uint32_t)(ar0 * MSTRIDE + ak0) * 2;
    const uint32_t s1 = (uint32_t)(ar1 * MSTRIDE + ak1) * 2;

    float acc[4][4][4];
#pragma unroll
    for (int mi = 0; mi < 4; mi++)
#pragma unroll
        for (int ni = 0; ni < 4; ni++)
#pragma unroll
            for (int rr = 0; rr < 4; rr++) acc[mi][ni][rr] = 0.f;

    uint4 rg[4];
    const int T = SEQ >> 5;

#define PLOADG(K0) do {                                                \
        rg[0] = *(const uint4*)(pP + gA0 + (K0));                      \
        rg[1] = *(const uint4*)(pP + gA1 + (K0));                      \
        rg[2] = *(const uint4*)(pV + gB0 + (K0));                      \
        rg[3] = *(const uint4*)(pV + gB1 + (K0));                      \
    } while (0)
#define PSTORES(S) do {                                                \
        char* base = smem + (S) * 2 * TILE_B;                          \
        *(uint4*)(base + s0)          = rg[0];                         \
        *(uint4*)(base + s1)          = rg[1];                         \
        *(uint4*)(base + TILE_B + s0) = rg[2];                         \
        *(uint4*)(base + TILE_B + s1) = rg[3];                         \
    } while (0)

    const int arow = warp_m * 64 + (lane & 15);
    const int acol = (lane >> 4) * 8;
    const int brow = warp_n * 32 + (lane & 7);
    const int bcol = ((lane >> 3) & 1) * 8;

    PLOADG(0);
    PSTORES(0);
    __syncthreads();

    for (int t = 0; t < T; t++) {
        if (t + 1 < T) PLOADG((t + 1) << 5);
        uint32_t base = sb + (uint32_t)(t & 1) * 2 * TILE_B;
#pragma unroll
        for (int kk = 0; kk < 32; kk += 16) {
            uint32_t ah[4][4], bh[4][2];
#pragma unroll
            for (int mi = 0; mi < 4; mi++) {
                uint32_t ad = (uint32_t)(((arow + mi * 16) * MSTRIDE + kk + acol) * 2);
                ldmx4(ah[mi], base + ad);
            }
#pragma unroll
            for (int ni = 0; ni < 4; ni++) {
                uint32_t bd = (uint32_t)(((brow + ni * 8) * MSTRIDE + kk + bcol) * 2);
                ldmx2(bh[ni], base + TILE_B + bd);
            }
#pragma unroll
            for (int mi = 0; mi < 4; mi++)
#pragma unroll
                for (int ni = 0; ni < 4; ni++)
                    mma_f16(acc[mi][ni], ah[mi], bh[ni]);
        }
        if (t + 1 < T) {
            PSTORES((t + 1) & 1);
            __syncthreads();
        }
    }
#undef PLOADG
#undef PSTORES

    float* C = Cout + (size_t)z * SEQ * DIM;
#pragma unroll
    for (int mi = 0; mi < 4; mi++) {
        int rowl = warp_m * 64 + mi * 16 + (lane >> 2);
        float inv0 = g_inv[z * SEQ + m0 + rowl];
        float inv1 = g_inv[z * SEQ + m0 + rowl + 8];
#pragma unroll
        for (int ni = 0; ni < 4; ni++) {
            int col = n0 + warp_n * 32 + ni * 8 + (lane & 3) * 2;
            *(float2*)&C[(size_t)(m0 + rowl) * DIM + col] =
                make_float2(acc[mi][ni][0] * inv0, acc[mi][ni][1] * inv0);
            *(float2*)&C[(size_t)(m0 + rowl + 8) * DIM + col] =
                make_float2(acc[mi][ni][2] * inv1, acc[mi][ni][3] * inv1);
        }
    }
}

// ======================= launch =============================================
extern "C" void kernel_launch(void* const* d_in, const int* in_sizes, int n_in,
                              void* d_out, int out_size)
{
    const float* x     = (const float*)d_in[0];
    const float* basis = (const float*)d_in[1];
    const float* Wq    = (const float*)d_in[2];
    const float* bq    = (const float*)d_in[3];
    const float* Wk    = (const float*)d_in[4];
    const float* bk    = (const float*)d_in[5];
    const float* Wv    = (const float*)d_in[6];
    const float* bv    = (const float*)d_in[7];
    float* out = (float*)d_out;

    __half *pxf, *pwf;
    cudaGetSymbolAddress((void**)&pxf, g_xf);
    cudaGetSymbolAddress((void**)&pwf, g_wf);

    cudaFuncSetAttribute(mma_gemm_xw, cudaFuncAttributeMaxDynamicSharedMemorySize, GM_SMEM);
    cudaFuncSetAttribute(mma_gemm_pv, cudaFuncAttributeMaxDynamicSharedMemorySize, GM_SMEM);

    // fp16 conversions
    tohalf_kernel<<<MTOK * DIM / 4 / 256, 256>>>(x, pxf);
    tohalf_kernel<<<DIM * DIM / 4 / 256, 256>>>(Wv, pwf);

    // fold (fp16 C + biases + maxk reset)
    fold_kernel<<<dim3(4, 32), 256>>>(basis, Wq, bq, Wk, bk);

    // kan via mma.sync (fp16 single-product) + per-batch key max
    kan_mma_kernel<<<MTOK / 64, 128>>>();
    knorm_kernel<<<MTOK / 256, 256>>>();

    // K3: v = x @ Wv^T + bv  -> vT fp16 (single product, 2 CTAs/SM)
    mma_gemm_xw<<<dim3(DIM / 128, MTOK / 128, 1), 256, GM_SMEM>>>(bv);

    // K4: fused scores + softmax (unnormalized exp fp16 + 1/sum)
    attn_kernel<<<MTOK / 64, 256>>>();

    // K5: out = (P @ v) * inv_sum  (single product, 2 CTAs/SM)
    mma_gemm_pv<<<dim3(DIM / 128, SEQ / 128, NB), 256, GM_SMEM>>>(out);
}